// round 9
// baseline (speedup 1.0000x reference)
#include <cuda_runtime.h>
#include <cuda_bf16.h>
#include <cstdint>

// ---------------------------------------------------------------------------
// SuperpixelAttention GB300 — Round 7: R5 tiled attention + cp.async halo
// pipelining (k-halo hidden behind simdot, v-halo hidden behind softmax).
//   conv_x : x fp32 -> g_x2 [pix][hi256|lo256] bf16
//   conv_w : Wq|Wk|Wv -> g_w1 (q scale folded), Wp -> g_w2
//   gemm(0): q/k/v fp32 (mma.sync bf16 3-term split)
//   attn   : 16x4 px tiles, 512 thr, k/v halo in smem, writes g_o2 bf16 hi|lo
//   gemm(1): out = o @ Wp, transposed store to [T,C,H,W]
// ---------------------------------------------------------------------------

#define NPIX 262144
#define NELEM 67108864

__device__ float g_q[NELEM];
__device__ float g_k[NELEM];
__device__ float g_v[NELEM];
__device__ __nv_bfloat16 g_x2[NPIX * 512];
__device__ __nv_bfloat16 g_o2[NPIX * 512];
__device__ __nv_bfloat16 g_w1[768 * 512];
__device__ __nv_bfloat16 g_w2[256 * 512];

__device__ __forceinline__ uint32_t smem_u32(const void* p) {
  uint32_t a;
  asm("{ .reg .u64 t; cvta.to.shared.u64 t, %1; cvt.u32.u64 %0, t; }"
      : "=r"(a) : "l"(p));
  return a;
}
#define SW128(o) ((o) ^ (((o) >> 3) & 0x70))

__device__ __forceinline__ void ldsm4(uint32_t& r0, uint32_t& r1, uint32_t& r2,
                                      uint32_t& r3, uint32_t a) {
  asm volatile("ldmatrix.sync.aligned.m8n8.x4.shared.b16 {%0,%1,%2,%3}, [%4];"
               : "=r"(r0), "=r"(r1), "=r"(r2), "=r"(r3) : "r"(a));
}
__device__ __forceinline__ void mma16816(float* c, const uint32_t* a,
                                         const uint32_t* b) {
  asm volatile(
      "mma.sync.aligned.m16n8k16.row.col.f32.bf16.bf16.f32 "
      "{%0,%1,%2,%3},{%4,%5,%6,%7},{%8,%9},{%0,%1,%2,%3};"
      : "+f"(c[0]), "+f"(c[1]), "+f"(c[2]), "+f"(c[3])
      : "r"(a[0]), "r"(a[1]), "r"(a[2]), "r"(a[3]), "r"(b[0]), "r"(b[1]));
}
__device__ __forceinline__ void cp16(uint32_t s, const void* g) {
  asm volatile("cp.async.cg.shared.global [%0], [%1], 16;" :: "r"(s), "l"(g));
}
#define CP_COMMIT() asm volatile("cp.async.commit_group;" ::: "memory")
#define CP_WAIT0()  asm volatile("cp.async.wait_group 0;" ::: "memory")

// ---------------------------------------------------------------------------
// Conversions
// ---------------------------------------------------------------------------
__global__ void __launch_bounds__(256) conv_x(const float* __restrict__ x) {
  extern __shared__ float xs[];  // 256 * 65
  const int tid = threadIdx.x;
  const int pix0 = blockIdx.x * 64;
  const int t = pix0 >> 16, h = (pix0 >> 8) & 255, w0 = pix0 & 255;
  const size_t base = (size_t)t * 16777216 + h * 256 + w0;
  for (int i = tid; i < 16384; i += 256) {
    int c = i >> 6, p = i & 63;
    xs[c * 65 + p] = x[base + (size_t)c * 65536 + p];
  }
  __syncthreads();
  for (int i = tid; i < 32768; i += 256) {
    int p = i >> 9, kk = i & 511, c = kk & 255;
    float v = xs[c * 65 + p];
    __nv_bfloat16 hi = __float2bfloat16_rn(v);
    __nv_bfloat16 o = (kk < 256) ? hi : __float2bfloat16_rn(v - __bfloat162float(hi));
    g_x2[(size_t)(pix0 + p) * 512 + kk] = o;
  }
}

__global__ void __launch_bounds__(256) conv_w(const float* __restrict__ Wq,
                                              const float* __restrict__ Wk,
                                              const float* __restrict__ Wv,
                                              const float* __restrict__ Wp) {
  const int n = blockIdx.x;   // 0..1023
  const int c = threadIdx.x;
  float v;
  __nv_bfloat16* dst;
  if (n < 768) {
    const float* Wm = (n < 256) ? Wq : ((n < 512) ? Wk : Wv);
    v = Wm[c * 256 + (n & 255)];
    if (n < 256) v *= 0.125f;  // fold hd^-0.5 into Wq
    dst = g_w1 + (size_t)n * 512;
  } else {
    v = Wp[c * 256 + (n & 255)];
    dst = g_w2 + (size_t)(n - 768) * 512;
  }
  __nv_bfloat16 hi = __float2bfloat16_rn(v);
  dst[c] = hi;
  dst[256 + c] = __float2bfloat16_rn(v - __bfloat162float(hi));
}

// ---------------------------------------------------------------------------
// mma.sync GEMM (unchanged from R4)
// ---------------------------------------------------------------------------
__global__ void __launch_bounds__(256) gemm_kernel(
    const __nv_bfloat16* __restrict__ A2,
    const __nv_bfloat16* __restrict__ B2,
    float* __restrict__ y, int mode) {
  extern __shared__ char dsm[];
  char* base = (char*)((((uintptr_t)dsm) + 1023) & ~(uintptr_t)1023);
  const uint32_t As_a = smem_u32(base);
  const uint32_t Bs_a0 = As_a + 131072u;
  float* ys = (float*)(base + 163840);

  const int tid = threadIdx.x, lane = tid & 31, wid = tid >> 5;
  const int wm = wid & 1, wn = wid >> 1;
  const int pix0 = blockIdx.x * 128;

  const uint4* Aq = (const uint4*)A2;
  for (int idx = tid; idx < 8192; idx += 256) {
    int ch = idx >> 10, row = (idx >> 3) & 127, c = idx & 7;
    *(uint4*)(base + ch * 16384 + SW128((uint32_t)(row * 128 + c * 16))) =
        Aq[(size_t)(pix0 + row) * 64 + ch * 8 + c];
  }

  const uint4* Bq = (const uint4*)B2;
  const int total = (mode ? 2 : 6) * 12;

  auto prefetchB = [&](int q) {
    int kc2 = q % 12, term = kc2 >> 2;
    int n0g = (q / 12) << 7;
    int b8 = ((term == 1) ? 32 : 0) + (kc2 & 3) * 8;
    uint32_t buf = Bs_a0 + (uint32_t)((q & 1) << 14);
    for (int idx = tid; idx < 1024; idx += 256) {
      int row = idx >> 3, c = idx & 7;
      cp16(buf + SW128((uint32_t)(row * 128 + c * 16)),
           &Bq[(size_t)(n0g + row) * 64 + b8 + c]);
    }
    CP_COMMIT();
  };

  float acc[4][4][4];
#pragma unroll
  for (int i = 0; i < 4; i++)
#pragma unroll
    for (int j = 0; j < 4; j++)
#pragma unroll
      for (int r = 0; r < 4; r++) acc[i][j][r] = 0.f;

  prefetchB(0);

  const int arow_off = (lane & 7) + ((lane >> 3) & 1) * 8;
  const int ak_ex = ((lane >> 4) & 1) * 16;
  const int brow_off = (lane & 7) + ((lane >> 4) & 1) * 8;
  const int bk_ex = ((lane >> 3) & 1) * 16;

  for (int q = 0; q < total; ++q) {
    if (q + 1 < total) {
      prefetchB(q + 1);
      asm volatile("cp.async.wait_group 1;" ::: "memory");
    } else {
      CP_WAIT0();
    }
    __syncthreads();

    const int kc2 = q % 12, term = kc2 >> 2;
    const uint32_t Ab = As_a + (uint32_t)((((term == 2) ? 4 : 0) + (kc2 & 3)) * 16384);
    const uint32_t Bb = Bs_a0 + (uint32_t)((q & 1) << 14);

#pragma unroll
    for (int s = 0; s < 4; ++s) {
      uint32_t af[4][4];
#pragma unroll
      for (int i = 0; i < 4; ++i) {
        uint32_t off = (uint32_t)((wm * 64 + i * 16 + arow_off) * 128 + s * 32 + ak_ex);
        ldsm4(af[i][0], af[i][1], af[i][2], af[i][3], Ab + SW128(off));
      }
      uint32_t bf[4][2];
#pragma unroll
      for (int j2 = 0; j2 < 2; ++j2) {
        uint32_t off = (uint32_t)((wn * 32 + j2 * 16 + brow_off) * 128 + s * 32 + bk_ex);
        ldsm4(bf[2 * j2][0], bf[2 * j2][1], bf[2 * j2 + 1][0], bf[2 * j2 + 1][1],
              Bb + SW128(off));
      }
#pragma unroll
      for (int i = 0; i < 4; ++i)
#pragma unroll
        for (int j = 0; j < 4; ++j) mma16816(acc[i][j], af[i], bf[j]);
    }

    if (kc2 == 11) {
      const int nc = q / 12;
      if (mode == 0) {
        float* dst = (nc < 2) ? g_q : (nc < 4) ? g_k : g_v;
        const int colb = (nc & 1) * 128 + wn * 32;
#pragma unroll
        for (int i = 0; i < 4; ++i) {
          int row0 = pix0 + wm * 64 + i * 16 + (lane >> 2);
#pragma unroll
          for (int j = 0; j < 4; ++j) {
            int col = colb + j * 8 + 2 * (lane & 3);
            *(float2*)(dst + (size_t)row0 * 256 + col) =
                make_float2(acc[i][j][0], acc[i][j][1]);
            *(float2*)(dst + (size_t)(row0 + 8) * 256 + col) =
                make_float2(acc[i][j][2], acc[i][j][3]);
          }
        }
      } else {
        const int t = pix0 >> 16, h = (pix0 >> 8) & 255, w0 = pix0 & 255;
        float* yb = y + (size_t)t * 16777216 + h * 256 + w0;
        for (int g = 0; g < 4; ++g) {
          if (wn == g) {
#pragma unroll
            for (int i = 0; i < 4; ++i) {
              int row0 = wm * 64 + i * 16 + (lane >> 2);
#pragma unroll
              for (int j = 0; j < 4; ++j) {
                int cl = j * 8 + 2 * (lane & 3);
                ys[cl * 132 + row0] = acc[i][j][0];
                ys[(cl + 1) * 132 + row0] = acc[i][j][1];
                ys[cl * 132 + row0 + 8] = acc[i][j][2];
                ys[(cl + 1) * 132 + row0 + 8] = acc[i][j][3];
              }
            }
          }
          __syncthreads();
          const int chb = nc * 128 + g * 32;
          for (int idx = tid; idx < 4096; idx += 256) {
            int cl = idx >> 7, p = idx & 127;
            yb[(size_t)(chb + cl) * 65536 + p] = ys[cl * 132 + p];
          }
          __syncthreads();
        }
      }
#pragma unroll
      for (int i = 0; i < 4; i++)
#pragma unroll
        for (int j = 0; j < 4; j++)
#pragma unroll
          for (int r = 0; r < 4; r++) acc[i][j][r] = 0.f;
    }
    __syncthreads();
  }
}

// ---------------------------------------------------------------------------
// Tiled attention (R5 structure) + cp.async halo pipelining.
// Block = 16(w) x 4(h) pixels, 512 threads (16 warps).
// Phases: [cp.async k-halo || sims+simdot] -> logits -> [cp.async v-halo ||
// softmax] -> accumulate -> store g_o2 bf16 hi|lo.
// ---------------------------------------------------------------------------
__device__ __forceinline__ uint32_t packbf2(float a, float b) {
  __nv_bfloat162 h = __floats2bfloat162_rn(a, b);
  return *reinterpret_cast<uint32_t*>(&h);
}

__global__ void __launch_bounds__(512) attn_kernel(const float* __restrict__ sims) {
  extern __shared__ float sm[];
  float* hs = sm;             // 40960 floats (160 cells x 256 ch)
  float* ls = sm + 40960;     // 6656: logits/wts [64][4][26]
  float* sd = ls + 6656;      // 1664: simdot [64][26]
  float* ss = sd + 1664;      // 1440: sims halo [9][160]

  const int tid = threadIdx.x, lane = tid & 31, wid = tid >> 5;
  const int bw = blockIdx.x & 15;
  const int bh = (blockIdx.x >> 4) & 63;
  const int t = blockIdx.x >> 10;
  const int w0 = bw << 4, h0 = bh << 2;
  const uint32_t hs_a = smem_u32(hs);

  // async halo load: 160 cells x 1KB, 20 cp16 per thread
  auto halo_async = [&](const float* src) {
    const char* s = (const char*)src;
#pragma unroll 1
    for (int i = tid; i < 10240; i += 512) {
      int cell = i >> 6, c4 = i & 63;
      int rr = cell / 20, cc = cell - rr * 20;
      int gh = min(max(h0 - 2 + rr, 0), 255);
      int gw = min(max(w0 - 2 + cc, 0), 255);
      cp16(hs_a + (uint32_t)(cell * 1024 + c4 * 16),
           s + ((size_t)((t << 16) | (gh << 8) | gw) * 64 + c4) * 16);
    }
    CP_COMMIT();
  };

  // ---- P0: k halo async || sims halo + simdot ----
  halo_async(g_k);
  for (int i = tid; i < 1440; i += 512) {
    int s = i / 160, cell = i - s * 160;
    int rr = cell / 20, cc = cell - rr * 20;
    int gh = min(max(h0 - 2 + rr, 0), 255);
    int gw = min(max(w0 - 2 + cc, 0), 255);
    ss[i] = sims[(size_t)(((t * 9 + s) << 16) | (gh << 8) | gw)];
  }
  __syncthreads();  // ss visible
  for (int i = tid; i < 1600; i += 512) {
    int px = i / 25, tap = i - px * 25;
    int r = px >> 4, wc = px & 15;
    int di = tap / 5, dj = tap - di * 5;
    int ctr = (r + 2) * 20 + wc + 2;
    int nbc = (r + di) * 20 + wc + dj;
    float acc = 0.f;
#pragma unroll
    for (int s = 0; s < 9; ++s) acc += ss[s * 160 + ctr] * ss[s * 160 + nbc];
    sd[px * 26 + tap] = acc;
  }
  CP_WAIT0();
  __syncthreads();  // k halo + sd visible

  // ---- P1: logits ----
  const int r = wid & 3, seg = wid >> 2;
  const int hgrp = lane >> 3;
  const size_t pixg0 = (size_t)((t << 16) | ((h0 + r) << 8) | (w0 + (seg << 2)));
  const float4* qg = (const float4*)g_q;
  float4 qa[4], qb[4];
#pragma unroll
  for (int p = 0; p < 4; ++p) {
    qa[p] = qg[(pixg0 + p) * 64 + lane * 2];
    qb[p] = qg[(pixg0 + p) * 64 + lane * 2 + 1];
  }

#pragma unroll 1
  for (int di = 0; di < 5; ++di) {
#pragma unroll
    for (int j = 0; j < 8; ++j) {
      const float4* kr = (const float4*)(hs + ((r + di) * 20 + (seg << 2) + j) * 256);
      float4 ka = kr[lane * 2], kb = kr[lane * 2 + 1];
      const int plo = (j - 4 > 0) ? j - 4 : 0;
      const int phi = (j < 3) ? j : 3;
#pragma unroll
      for (int p = plo; p <= phi; ++p) {
        float d = qa[p].x * ka.x + qa[p].y * ka.y + qa[p].z * ka.z + qa[p].w * ka.w +
                  qb[p].x * kb.x + qb[p].y * kb.y + qb[p].z * kb.z + qb[p].w * kb.w;
        d += __shfl_xor_sync(0xffffffffu, d, 1);
        d += __shfl_xor_sync(0xffffffffu, d, 2);
        d += __shfl_xor_sync(0xffffffffu, d, 4);
        if ((lane & 7) == 0) {
          int px = (r << 4) + (seg << 2) + p;
          ls[(px * 4 + hgrp) * 26 + di * 5 + j - p] = d;
        }
      }
    }
  }
  __syncthreads();  // all warps done reading k halo; ls complete

  // ---- P2: v halo async || softmax + sim reweight (in place in ls) ----
  halo_async(g_v);
#pragma unroll 1
  for (int p = 0; p < 4; ++p) {
    const int px = (r << 4) + (seg << 2) + p;
#pragma unroll 1
    for (int h4 = 0; h4 < 4; ++h4) {
      float a = (lane < 25) ? ls[(px * 4 + h4) * 26 + lane] : -1e30f;
      float mx = a;
      mx = fmaxf(mx, __shfl_xor_sync(0xffffffffu, mx, 16));
      mx = fmaxf(mx, __shfl_xor_sync(0xffffffffu, mx, 8));
      mx = fmaxf(mx, __shfl_xor_sync(0xffffffffu, mx, 4));
      mx = fmaxf(mx, __shfl_xor_sync(0xffffffffu, mx, 2));
      mx = fmaxf(mx, __shfl_xor_sync(0xffffffffu, mx, 1));
      float e = (lane < 25) ? __expf(a - mx) * sd[px * 26 + lane] : 0.f;
      float s = e;
      s += __shfl_xor_sync(0xffffffffu, s, 16);
      s += __shfl_xor_sync(0xffffffffu, s, 8);
      s += __shfl_xor_sync(0xffffffffu, s, 4);
      s += __shfl_xor_sync(0xffffffffu, s, 2);
      s += __shfl_xor_sync(0xffffffffu, s, 1);
      if (lane < 25) ls[(px * 4 + h4) * 26 + lane] = e / (1e-10f + s);
    }
  }
  CP_WAIT0();
  __syncthreads();  // v halo + wts visible

  // ---- P3: weighted accumulate ----
  float acc[4][8];
#pragma unroll
  for (int p = 0; p < 4; ++p)
#pragma unroll
    for (int c = 0; c < 8; ++c) acc[p][c] = 0.f;

#pragma unroll 1
  for (int di = 0; di < 5; ++di) {
#pragma unroll
    for (int j = 0; j < 8; ++j) {
      const float4* vr = (const float4*)(hs + ((r + di) * 20 + (seg << 2) + j) * 256);
      float4 va = vr[lane * 2], vb = vr[lane * 2 + 1];
      const int plo = (j - 4 > 0) ? j - 4 : 0;
      const int phi = (j < 3) ? j : 3;
#pragma unroll
      for (int p = plo; p <= phi; ++p) {
        int px = (r << 4) + (seg << 2) + p;
        float wt = ls[(px * 4 + hgrp) * 26 + di * 5 + j - p];
        acc[p][0] += wt * va.x; acc[p][1] += wt * va.y;
        acc[p][2] += wt * va.z; acc[p][3] += wt * va.w;
        acc[p][4] += wt * vb.x; acc[p][5] += wt * vb.y;
        acc[p][6] += wt * vb.z; acc[p][7] += wt * vb.w;
      }
    }
  }

  // ---- store g_o2 bf16 hi|lo directly ----
  uint4* oq = (uint4*)g_o2;
#pragma unroll
  for (int p = 0; p < 4; ++p) {
    float hi[8], lo[8];
#pragma unroll
    for (int c = 0; c < 8; ++c) {
      hi[c] = __bfloat162float(__float2bfloat16_rn(acc[p][c]));
      lo[c] = acc[p][c] - hi[c];
    }
    uint4 hv, lv;
    hv.x = packbf2(hi[0], hi[1]); hv.y = packbf2(hi[2], hi[3]);
    hv.z = packbf2(hi[4], hi[5]); hv.w = packbf2(hi[6], hi[7]);
    lv.x = packbf2(lo[0], lo[1]); lv.y = packbf2(lo[2], lo[3]);
    lv.z = packbf2(lo[4], lo[5]); lv.w = packbf2(lo[6], lo[7]);
    oq[(pixg0 + p) * 64 + lane] = hv;
    oq[(pixg0 + p) * 64 + 32 + lane] = lv;
  }
}

// ---------------------------------------------------------------------------
extern "C" void kernel_launch(void* const* d_in, const int* in_sizes, int n_in,
                              void* d_out, int out_size) {
  (void)in_sizes; (void)n_in; (void)out_size;
  const float* x = (const float*)d_in[0];
  const float* sims = (const float*)d_in[1];
  const float* Wq = (const float*)d_in[3];
  const float* Wk = (const float*)d_in[4];
  const float* Wv = (const float*)d_in[5];
  const float* Wp = (const float*)d_in[6];
  float* out = (float*)d_out;

  const int smem_cx = 256 * 65 * sizeof(float);
  const int smem_gm = 1024 + 163840 + 16896;
  const int smem_at = 50720 * sizeof(float);  // 202880 B
  cudaFuncSetAttribute(conv_x, cudaFuncAttributeMaxDynamicSharedMemorySize, smem_cx);
  cudaFuncSetAttribute(gemm_kernel, cudaFuncAttributeMaxDynamicSharedMemorySize, smem_gm);
  cudaFuncSetAttribute(attn_kernel, cudaFuncAttributeMaxDynamicSharedMemorySize, smem_at);

  __nv_bfloat16 *px2, *po2, *pw1, *pw2;
  cudaGetSymbolAddress((void**)&px2, g_x2);
  cudaGetSymbolAddress((void**)&po2, g_o2);
  cudaGetSymbolAddress((void**)&pw1, g_w1);
  cudaGetSymbolAddress((void**)&pw2, g_w2);

  conv_x<<<NPIX / 64, 256, smem_cx>>>(x);
  conv_w<<<1024, 256>>>(Wq, Wk, Wv, Wp);
  gemm_kernel<<<NPIX / 128, 256, smem_gm>>>(px2, pw1, nullptr, 0);
  attn_kernel<<<4096, 512, smem_at>>>(sims);
  gemm_kernel<<<NPIX / 128, 256, smem_gm>>>(po2, pw2, out, 1);
}

// round 10
// speedup vs baseline: 1.0041x; 1.0041x over previous
#include <cuda_runtime.h>
#include <cuda_bf16.h>
#include <cstdint>

// ---------------------------------------------------------------------------
// SuperpixelAttention GB300 — Round 7: R5 tiled attention + cp.async halo
// pipelining (k-halo hidden behind simdot, v-halo hidden behind softmax).
//   conv_x : x fp32 -> g_x2 [pix][hi256|lo256] bf16
//   conv_w : Wq|Wk|Wv -> g_w1 (q scale folded), Wp -> g_w2
//   gemm(0): q/k/v fp32 (mma.sync bf16 3-term split)
//   attn   : 16x4 px tiles, 512 thr, k/v halo in smem, writes g_o2 bf16 hi|lo
//   gemm(1): out = o @ Wp, transposed store to [T,C,H,W]
// ---------------------------------------------------------------------------

#define NPIX 262144
#define NELEM 67108864

__device__ float g_q[NELEM];
__device__ float g_k[NELEM];
__device__ float g_v[NELEM];
__device__ __nv_bfloat16 g_x2[NPIX * 512];
__device__ __nv_bfloat16 g_o2[NPIX * 512];
__device__ __nv_bfloat16 g_w1[768 * 512];
__device__ __nv_bfloat16 g_w2[256 * 512];

__device__ __forceinline__ uint32_t smem_u32(const void* p) {
  uint32_t a;
  asm("{ .reg .u64 t; cvta.to.shared.u64 t, %1; cvt.u32.u64 %0, t; }"
      : "=r"(a) : "l"(p));
  return a;
}
#define SW128(o) ((o) ^ (((o) >> 3) & 0x70))

__device__ __forceinline__ void ldsm4(uint32_t& r0, uint32_t& r1, uint32_t& r2,
                                      uint32_t& r3, uint32_t a) {
  asm volatile("ldmatrix.sync.aligned.m8n8.x4.shared.b16 {%0,%1,%2,%3}, [%4];"
               : "=r"(r0), "=r"(r1), "=r"(r2), "=r"(r3) : "r"(a));
}
__device__ __forceinline__ void mma16816(float* c, const uint32_t* a,
                                         const uint32_t* b) {
  asm volatile(
      "mma.sync.aligned.m16n8k16.row.col.f32.bf16.bf16.f32 "
      "{%0,%1,%2,%3},{%4,%5,%6,%7},{%8,%9},{%0,%1,%2,%3};"
      : "+f"(c[0]), "+f"(c[1]), "+f"(c[2]), "+f"(c[3])
      : "r"(a[0]), "r"(a[1]), "r"(a[2]), "r"(a[3]), "r"(b[0]), "r"(b[1]));
}
__device__ __forceinline__ void cp16(uint32_t s, const void* g) {
  asm volatile("cp.async.cg.shared.global [%0], [%1], 16;" :: "r"(s), "l"(g));
}
#define CP_COMMIT() asm volatile("cp.async.commit_group;" ::: "memory")
#define CP_WAIT0()  asm volatile("cp.async.wait_group 0;" ::: "memory")

// ---------------------------------------------------------------------------
// Conversions
// ---------------------------------------------------------------------------
__global__ void __launch_bounds__(256) conv_x(const float* __restrict__ x) {
  extern __shared__ float xs[];  // 256 * 65
  const int tid = threadIdx.x;
  const int pix0 = blockIdx.x * 64;
  const int t = pix0 >> 16, h = (pix0 >> 8) & 255, w0 = pix0 & 255;
  const size_t base = (size_t)t * 16777216 + h * 256 + w0;
  for (int i = tid; i < 16384; i += 256) {
    int c = i >> 6, p = i & 63;
    xs[c * 65 + p] = x[base + (size_t)c * 65536 + p];
  }
  __syncthreads();
  for (int i = tid; i < 32768; i += 256) {
    int p = i >> 9, kk = i & 511, c = kk & 255;
    float v = xs[c * 65 + p];
    __nv_bfloat16 hi = __float2bfloat16_rn(v);
    __nv_bfloat16 o = (kk < 256) ? hi : __float2bfloat16_rn(v - __bfloat162float(hi));
    g_x2[(size_t)(pix0 + p) * 512 + kk] = o;
  }
}

__global__ void __launch_bounds__(256) conv_w(const float* __restrict__ Wq,
                                              const float* __restrict__ Wk,
                                              const float* __restrict__ Wv,
                                              const float* __restrict__ Wp) {
  const int n = blockIdx.x;   // 0..1023
  const int c = threadIdx.x;
  float v;
  __nv_bfloat16* dst;
  if (n < 768) {
    const float* Wm = (n < 256) ? Wq : ((n < 512) ? Wk : Wv);
    v = Wm[c * 256 + (n & 255)];
    if (n < 256) v *= 0.125f;  // fold hd^-0.5 into Wq
    dst = g_w1 + (size_t)n * 512;
  } else {
    v = Wp[c * 256 + (n & 255)];
    dst = g_w2 + (size_t)(n - 768) * 512;
  }
  __nv_bfloat16 hi = __float2bfloat16_rn(v);
  dst[c] = hi;
  dst[256 + c] = __float2bfloat16_rn(v - __bfloat162float(hi));
}

// ---------------------------------------------------------------------------
// mma.sync GEMM (unchanged from R4)
// ---------------------------------------------------------------------------
__global__ void __launch_bounds__(256) gemm_kernel(
    const __nv_bfloat16* __restrict__ A2,
    const __nv_bfloat16* __restrict__ B2,
    float* __restrict__ y, int mode) {
  extern __shared__ char dsm[];
  char* base = (char*)((((uintptr_t)dsm) + 1023) & ~(uintptr_t)1023);
  const uint32_t As_a = smem_u32(base);
  const uint32_t Bs_a0 = As_a + 131072u;
  float* ys = (float*)(base + 163840);

  const int tid = threadIdx.x, lane = tid & 31, wid = tid >> 5;
  const int wm = wid & 1, wn = wid >> 1;
  const int pix0 = blockIdx.x * 128;

  const uint4* Aq = (const uint4*)A2;
  for (int idx = tid; idx < 8192; idx += 256) {
    int ch = idx >> 10, row = (idx >> 3) & 127, c = idx & 7;
    *(uint4*)(base + ch * 16384 + SW128((uint32_t)(row * 128 + c * 16))) =
        Aq[(size_t)(pix0 + row) * 64 + ch * 8 + c];
  }

  const uint4* Bq = (const uint4*)B2;
  const int total = (mode ? 2 : 6) * 12;

  auto prefetchB = [&](int q) {
    int kc2 = q % 12, term = kc2 >> 2;
    int n0g = (q / 12) << 7;
    int b8 = ((term == 1) ? 32 : 0) + (kc2 & 3) * 8;
    uint32_t buf = Bs_a0 + (uint32_t)((q & 1) << 14);
    for (int idx = tid; idx < 1024; idx += 256) {
      int row = idx >> 3, c = idx & 7;
      cp16(buf + SW128((uint32_t)(row * 128 + c * 16)),
           &Bq[(size_t)(n0g + row) * 64 + b8 + c]);
    }
    CP_COMMIT();
  };

  float acc[4][4][4];
#pragma unroll
  for (int i = 0; i < 4; i++)
#pragma unroll
    for (int j = 0; j < 4; j++)
#pragma unroll
      for (int r = 0; r < 4; r++) acc[i][j][r] = 0.f;

  prefetchB(0);

  const int arow_off = (lane & 7) + ((lane >> 3) & 1) * 8;
  const int ak_ex = ((lane >> 4) & 1) * 16;
  const int brow_off = (lane & 7) + ((lane >> 4) & 1) * 8;
  const int bk_ex = ((lane >> 3) & 1) * 16;

  for (int q = 0; q < total; ++q) {
    if (q + 1 < total) {
      prefetchB(q + 1);
      asm volatile("cp.async.wait_group 1;" ::: "memory");
    } else {
      CP_WAIT0();
    }
    __syncthreads();

    const int kc2 = q % 12, term = kc2 >> 2;
    const uint32_t Ab = As_a + (uint32_t)((((term == 2) ? 4 : 0) + (kc2 & 3)) * 16384);
    const uint32_t Bb = Bs_a0 + (uint32_t)((q & 1) << 14);

#pragma unroll
    for (int s = 0; s < 4; ++s) {
      uint32_t af[4][4];
#pragma unroll
      for (int i = 0; i < 4; ++i) {
        uint32_t off = (uint32_t)((wm * 64 + i * 16 + arow_off) * 128 + s * 32 + ak_ex);
        ldsm4(af[i][0], af[i][1], af[i][2], af[i][3], Ab + SW128(off));
      }
      uint32_t bf[4][2];
#pragma unroll
      for (int j2 = 0; j2 < 2; ++j2) {
        uint32_t off = (uint32_t)((wn * 32 + j2 * 16 + brow_off) * 128 + s * 32 + bk_ex);
        ldsm4(bf[2 * j2][0], bf[2 * j2][1], bf[2 * j2 + 1][0], bf[2 * j2 + 1][1],
              Bb + SW128(off));
      }
#pragma unroll
      for (int i = 0; i < 4; ++i)
#pragma unroll
        for (int j = 0; j < 4; ++j) mma16816(acc[i][j], af[i], bf[j]);
    }

    if (kc2 == 11) {
      const int nc = q / 12;
      if (mode == 0) {
        float* dst = (nc < 2) ? g_q : (nc < 4) ? g_k : g_v;
        const int colb = (nc & 1) * 128 + wn * 32;
#pragma unroll
        for (int i = 0; i < 4; ++i) {
          int row0 = pix0 + wm * 64 + i * 16 + (lane >> 2);
#pragma unroll
          for (int j = 0; j < 4; ++j) {
            int col = colb + j * 8 + 2 * (lane & 3);
            *(float2*)(dst + (size_t)row0 * 256 + col) =
                make_float2(acc[i][j][0], acc[i][j][1]);
            *(float2*)(dst + (size_t)(row0 + 8) * 256 + col) =
                make_float2(acc[i][j][2], acc[i][j][3]);
          }
        }
      } else {
        const int t = pix0 >> 16, h = (pix0 >> 8) & 255, w0 = pix0 & 255;
        float* yb = y + (size_t)t * 16777216 + h * 256 + w0;
        for (int g = 0; g < 4; ++g) {
          if (wn == g) {
#pragma unroll
            for (int i = 0; i < 4; ++i) {
              int row0 = wm * 64 + i * 16 + (lane >> 2);
#pragma unroll
              for (int j = 0; j < 4; ++j) {
                int cl = j * 8 + 2 * (lane & 3);
                ys[cl * 132 + row0] = acc[i][j][0];
                ys[(cl + 1) * 132 + row0] = acc[i][j][1];
                ys[cl * 132 + row0 + 8] = acc[i][j][2];
                ys[(cl + 1) * 132 + row0 + 8] = acc[i][j][3];
              }
            }
          }
          __syncthreads();
          const int chb = nc * 128 + g * 32;
          for (int idx = tid; idx < 4096; idx += 256) {
            int cl = idx >> 7, p = idx & 127;
            yb[(size_t)(chb + cl) * 65536 + p] = ys[cl * 132 + p];
          }
          __syncthreads();
        }
      }
#pragma unroll
      for (int i = 0; i < 4; i++)
#pragma unroll
        for (int j = 0; j < 4; j++)
#pragma unroll
          for (int r = 0; r < 4; r++) acc[i][j][r] = 0.f;
    }
    __syncthreads();
  }
}

// ---------------------------------------------------------------------------
// Tiled attention (R5 structure) + cp.async halo pipelining.
// Block = 16(w) x 4(h) pixels, 512 threads (16 warps).
// Phases: [cp.async k-halo || sims+simdot] -> logits -> [cp.async v-halo ||
// softmax] -> accumulate -> store g_o2 bf16 hi|lo.
// ---------------------------------------------------------------------------
__device__ __forceinline__ uint32_t packbf2(float a, float b) {
  __nv_bfloat162 h = __floats2bfloat162_rn(a, b);
  return *reinterpret_cast<uint32_t*>(&h);
}

__global__ void __launch_bounds__(512) attn_kernel(const float* __restrict__ sims) {
  extern __shared__ float sm[];
  float* hs = sm;             // 40960 floats (160 cells x 256 ch)
  float* ls = sm + 40960;     // 6656: logits/wts [64][4][26]
  float* sd = ls + 6656;      // 1664: simdot [64][26]
  float* ss = sd + 1664;      // 1440: sims halo [9][160]

  const int tid = threadIdx.x, lane = tid & 31, wid = tid >> 5;
  const int bw = blockIdx.x & 15;
  const int bh = (blockIdx.x >> 4) & 63;
  const int t = blockIdx.x >> 10;
  const int w0 = bw << 4, h0 = bh << 2;
  const uint32_t hs_a = smem_u32(hs);

  // async halo load: 160 cells x 1KB, 20 cp16 per thread
  auto halo_async = [&](const float* src) {
    const char* s = (const char*)src;
#pragma unroll 1
    for (int i = tid; i < 10240; i += 512) {
      int cell = i >> 6, c4 = i & 63;
      int rr = cell / 20, cc = cell - rr * 20;
      int gh = min(max(h0 - 2 + rr, 0), 255);
      int gw = min(max(w0 - 2 + cc, 0), 255);
      cp16(hs_a + (uint32_t)(cell * 1024 + c4 * 16),
           s + ((size_t)((t << 16) | (gh << 8) | gw) * 64 + c4) * 16);
    }
    CP_COMMIT();
  };

  // ---- P0: k halo async || sims halo + simdot ----
  halo_async(g_k);
  for (int i = tid; i < 1440; i += 512) {
    int s = i / 160, cell = i - s * 160;
    int rr = cell / 20, cc = cell - rr * 20;
    int gh = min(max(h0 - 2 + rr, 0), 255);
    int gw = min(max(w0 - 2 + cc, 0), 255);
    ss[i] = sims[(size_t)(((t * 9 + s) << 16) | (gh << 8) | gw)];
  }
  __syncthreads();  // ss visible
  for (int i = tid; i < 1600; i += 512) {
    int px = i / 25, tap = i - px * 25;
    int r = px >> 4, wc = px & 15;
    int di = tap / 5, dj = tap - di * 5;
    int ctr = (r + 2) * 20 + wc + 2;
    int nbc = (r + di) * 20 + wc + dj;
    float acc = 0.f;
#pragma unroll
    for (int s = 0; s < 9; ++s) acc += ss[s * 160 + ctr] * ss[s * 160 + nbc];
    sd[px * 26 + tap] = acc;
  }
  CP_WAIT0();
  __syncthreads();  // k halo + sd visible

  // ---- P1: logits ----
  const int r = wid & 3, seg = wid >> 2;
  const int hgrp = lane >> 3;
  const size_t pixg0 = (size_t)((t << 16) | ((h0 + r) << 8) | (w0 + (seg << 2)));
  const float4* qg = (const float4*)g_q;
  float4 qa[4], qb[4];
#pragma unroll
  for (int p = 0; p < 4; ++p) {
    qa[p] = qg[(pixg0 + p) * 64 + lane * 2];
    qb[p] = qg[(pixg0 + p) * 64 + lane * 2 + 1];
  }

#pragma unroll 1
  for (int di = 0; di < 5; ++di) {
#pragma unroll
    for (int j = 0; j < 8; ++j) {
      const float4* kr = (const float4*)(hs + ((r + di) * 20 + (seg << 2) + j) * 256);
      float4 ka = kr[lane * 2], kb = kr[lane * 2 + 1];
      const int plo = (j - 4 > 0) ? j - 4 : 0;
      const int phi = (j < 3) ? j : 3;
#pragma unroll
      for (int p = plo; p <= phi; ++p) {
        float d = qa[p].x * ka.x + qa[p].y * ka.y + qa[p].z * ka.z + qa[p].w * ka.w +
                  qb[p].x * kb.x + qb[p].y * kb.y + qb[p].z * kb.z + qb[p].w * kb.w;
        d += __shfl_xor_sync(0xffffffffu, d, 1);
        d += __shfl_xor_sync(0xffffffffu, d, 2);
        d += __shfl_xor_sync(0xffffffffu, d, 4);
        if ((lane & 7) == 0) {
          int px = (r << 4) + (seg << 2) + p;
          ls[(px * 4 + hgrp) * 26 + di * 5 + j - p] = d;
        }
      }
    }
  }
  __syncthreads();  // all warps done reading k halo; ls complete

  // ---- P2: v halo async || softmax + sim reweight (in place in ls) ----
  halo_async(g_v);
#pragma unroll 1
  for (int p = 0; p < 4; ++p) {
    const int px = (r << 4) + (seg << 2) + p;
#pragma unroll 1
    for (int h4 = 0; h4 < 4; ++h4) {
      float a = (lane < 25) ? ls[(px * 4 + h4) * 26 + lane] : -1e30f;
      float mx = a;
      mx = fmaxf(mx, __shfl_xor_sync(0xffffffffu, mx, 16));
      mx = fmaxf(mx, __shfl_xor_sync(0xffffffffu, mx, 8));
      mx = fmaxf(mx, __shfl_xor_sync(0xffffffffu, mx, 4));
      mx = fmaxf(mx, __shfl_xor_sync(0xffffffffu, mx, 2));
      mx = fmaxf(mx, __shfl_xor_sync(0xffffffffu, mx, 1));
      float e = (lane < 25) ? __expf(a - mx) * sd[px * 26 + lane] : 0.f;
      float s = e;
      s += __shfl_xor_sync(0xffffffffu, s, 16);
      s += __shfl_xor_sync(0xffffffffu, s, 8);
      s += __shfl_xor_sync(0xffffffffu, s, 4);
      s += __shfl_xor_sync(0xffffffffu, s, 2);
      s += __shfl_xor_sync(0xffffffffu, s, 1);
      if (lane < 25) ls[(px * 4 + h4) * 26 + lane] = e / (1e-10f + s);
    }
  }
  CP_WAIT0();
  __syncthreads();  // v halo + wts visible

  // ---- P3: weighted accumulate ----
  float acc[4][8];
#pragma unroll
  for (int p = 0; p < 4; ++p)
#pragma unroll
    for (int c = 0; c < 8; ++c) acc[p][c] = 0.f;

#pragma unroll 1
  for (int di = 0; di < 5; ++di) {
#pragma unroll
    for (int j = 0; j < 8; ++j) {
      const float4* vr = (const float4*)(hs + ((r + di) * 20 + (seg << 2) + j) * 256);
      float4 va = vr[lane * 2], vb = vr[lane * 2 + 1];
      const int plo = (j - 4 > 0) ? j - 4 : 0;
      const int phi = (j < 3) ? j : 3;
#pragma unroll
      for (int p = plo; p <= phi; ++p) {
        int px = (r << 4) + (seg << 2) + p;
        float wt = ls[(px * 4 + hgrp) * 26 + di * 5 + j - p];
        acc[p][0] += wt * va.x; acc[p][1] += wt * va.y;
        acc[p][2] += wt * va.z; acc[p][3] += wt * va.w;
        acc[p][4] += wt * vb.x; acc[p][5] += wt * vb.y;
        acc[p][6] += wt * vb.z; acc[p][7] += wt * vb.w;
      }
    }
  }

  // ---- store g_o2 bf16 hi|lo directly ----
  uint4* oq = (uint4*)g_o2;
#pragma unroll
  for (int p = 0; p < 4; ++p) {
    float hi[8], lo[8];
#pragma unroll
    for (int c = 0; c < 8; ++c) {
      hi[c] = __bfloat162float(__float2bfloat16_rn(acc[p][c]));
      lo[c] = acc[p][c] - hi[c];
    }
    uint4 hv, lv;
    hv.x = packbf2(hi[0], hi[1]); hv.y = packbf2(hi[2], hi[3]);
    hv.z = packbf2(hi[4], hi[5]); hv.w = packbf2(hi[6], hi[7]);
    lv.x = packbf2(lo[0], lo[1]); lv.y = packbf2(lo[2], lo[3]);
    lv.z = packbf2(lo[4], lo[5]); lv.w = packbf2(lo[6], lo[7]);
    oq[(pixg0 + p) * 64 + lane] = hv;
    oq[(pixg0 + p) * 64 + 32 + lane] = lv;
  }
}

// ---------------------------------------------------------------------------
extern "C" void kernel_launch(void* const* d_in, const int* in_sizes, int n_in,
                              void* d_out, int out_size) {
  (void)in_sizes; (void)n_in; (void)out_size;
  const float* x = (const float*)d_in[0];
  const float* sims = (const float*)d_in[1];
  const float* Wq = (const float*)d_in[3];
  const float* Wk = (const float*)d_in[4];
  const float* Wv = (const float*)d_in[5];
  const float* Wp = (const float*)d_in[6];
  float* out = (float*)d_out;

  const int smem_cx = 256 * 65 * sizeof(float);
  const int smem_gm = 1024 + 163840 + 16896;
  const int smem_at = 50720 * sizeof(float);  // 202880 B
  cudaFuncSetAttribute(conv_x, cudaFuncAttributeMaxDynamicSharedMemorySize, smem_cx);
  cudaFuncSetAttribute(gemm_kernel, cudaFuncAttributeMaxDynamicSharedMemorySize, smem_gm);
  cudaFuncSetAttribute(attn_kernel, cudaFuncAttributeMaxDynamicSharedMemorySize, smem_at);

  __nv_bfloat16 *px2, *po2, *pw1, *pw2;
  cudaGetSymbolAddress((void**)&px2, g_x2);
  cudaGetSymbolAddress((void**)&po2, g_o2);
  cudaGetSymbolAddress((void**)&pw1, g_w1);
  cudaGetSymbolAddress((void**)&pw2, g_w2);

  conv_x<<<NPIX / 64, 256, smem_cx>>>(x);
  conv_w<<<1024, 256>>>(Wq, Wk, Wv, Wp);
  gemm_kernel<<<NPIX / 128, 256, smem_gm>>>(px2, pw1, nullptr, 0);
  attn_kernel<<<4096, 512, smem_at>>>(sims);
  gemm_kernel<<<NPIX / 128, 256, smem_gm>>>(po2, pw2, out, 1);
}

// round 11
// speedup vs baseline: 1.1025x; 1.0981x over previous
#include <cuda_runtime.h>
#include <cuda_bf16.h>
#include <cstdint>

// ---------------------------------------------------------------------------
// SuperpixelAttention GB300 — Round 10: 8x4-tile attention (2 blocks/SM,
// independent barrier domains) + single-sync gemm mainloop.
//   conv_x : x fp32 -> g_x2 [pix][hi256|lo256] bf16
//   conv_w : Wq|Wk|Wv -> g_w1 (q scale folded), Wp -> g_w2
//   gemm(0): q/k/v fp32 (mma.sync bf16 3-term split)
//   attn   : 8x4 px tiles, 256 thr, k/v halo cp.async-pipelined, ~112KB smem
//   gemm(1): out = o @ Wp, transposed store to [T,C,H,W]
// ---------------------------------------------------------------------------

#define NPIX 262144
#define NELEM 67108864

__device__ float g_q[NELEM];
__device__ float g_k[NELEM];
__device__ float g_v[NELEM];
__device__ __nv_bfloat16 g_x2[NPIX * 512];
__device__ __nv_bfloat16 g_o2[NPIX * 512];
__device__ __nv_bfloat16 g_w1[768 * 512];
__device__ __nv_bfloat16 g_w2[256 * 512];

__device__ __forceinline__ uint32_t smem_u32(const void* p) {
  uint32_t a;
  asm("{ .reg .u64 t; cvta.to.shared.u64 t, %1; cvt.u32.u64 %0, t; }"
      : "=r"(a) : "l"(p));
  return a;
}
#define SW128(o) ((o) ^ (((o) >> 3) & 0x70))

__device__ __forceinline__ void ldsm4(uint32_t& r0, uint32_t& r1, uint32_t& r2,
                                      uint32_t& r3, uint32_t a) {
  asm volatile("ldmatrix.sync.aligned.m8n8.x4.shared.b16 {%0,%1,%2,%3}, [%4];"
               : "=r"(r0), "=r"(r1), "=r"(r2), "=r"(r3) : "r"(a));
}
__device__ __forceinline__ void mma16816(float* c, const uint32_t* a,
                                         const uint32_t* b) {
  asm volatile(
      "mma.sync.aligned.m16n8k16.row.col.f32.bf16.bf16.f32 "
      "{%0,%1,%2,%3},{%4,%5,%6,%7},{%8,%9},{%0,%1,%2,%3};"
      : "+f"(c[0]), "+f"(c[1]), "+f"(c[2]), "+f"(c[3])
      : "r"(a[0]), "r"(a[1]), "r"(a[2]), "r"(a[3]), "r"(b[0]), "r"(b[1]));
}
__device__ __forceinline__ void cp16(uint32_t s, const void* g) {
  asm volatile("cp.async.cg.shared.global [%0], [%1], 16;" :: "r"(s), "l"(g));
}
#define CP_COMMIT() asm volatile("cp.async.commit_group;" ::: "memory")
#define CP_WAIT0()  asm volatile("cp.async.wait_group 0;" ::: "memory")

// ---------------------------------------------------------------------------
// Conversions
// ---------------------------------------------------------------------------
__global__ void __launch_bounds__(256) conv_x(const float* __restrict__ x) {
  extern __shared__ float xs[];  // 256 * 65
  const int tid = threadIdx.x;
  const int pix0 = blockIdx.x * 64;
  const int t = pix0 >> 16, h = (pix0 >> 8) & 255, w0 = pix0 & 255;
  const size_t base = (size_t)t * 16777216 + h * 256 + w0;
  for (int i = tid; i < 16384; i += 256) {
    int c = i >> 6, p = i & 63;
    xs[c * 65 + p] = x[base + (size_t)c * 65536 + p];
  }
  __syncthreads();
  for (int i = tid; i < 32768; i += 256) {
    int p = i >> 9, kk = i & 511, c = kk & 255;
    float v = xs[c * 65 + p];
    __nv_bfloat16 hi = __float2bfloat16_rn(v);
    __nv_bfloat16 o = (kk < 256) ? hi : __float2bfloat16_rn(v - __bfloat162float(hi));
    g_x2[(size_t)(pix0 + p) * 512 + kk] = o;
  }
}

__global__ void __launch_bounds__(256) conv_w(const float* __restrict__ Wq,
                                              const float* __restrict__ Wk,
                                              const float* __restrict__ Wv,
                                              const float* __restrict__ Wp) {
  const int n = blockIdx.x;   // 0..1023
  const int c = threadIdx.x;
  float v;
  __nv_bfloat16* dst;
  if (n < 768) {
    const float* Wm = (n < 256) ? Wq : ((n < 512) ? Wk : Wv);
    v = Wm[c * 256 + (n & 255)];
    if (n < 256) v *= 0.125f;  // fold hd^-0.5 into Wq
    dst = g_w1 + (size_t)n * 512;
  } else {
    v = Wp[c * 256 + (n & 255)];
    dst = g_w2 + (size_t)(n - 768) * 512;
  }
  __nv_bfloat16 hi = __float2bfloat16_rn(v);
  dst[c] = hi;
  dst[256 + c] = __float2bfloat16_rn(v - __bfloat162float(hi));
}

// ---------------------------------------------------------------------------
// mma.sync GEMM — single __syncthreads per K-chunk:
//   wait_group 0 (chunk q landed; whole prior mma-phase was the overlap
//   window) -> sync -> prefetch chunk q+1 -> ldsm/mma on chunk q.
// ---------------------------------------------------------------------------
__global__ void __launch_bounds__(256) gemm_kernel(
    const __nv_bfloat16* __restrict__ A2,
    const __nv_bfloat16* __restrict__ B2,
    float* __restrict__ y, int mode) {
  extern __shared__ char dsm[];
  char* base = (char*)((((uintptr_t)dsm) + 1023) & ~(uintptr_t)1023);
  const uint32_t As_a = smem_u32(base);
  const uint32_t Bs_a0 = As_a + 131072u;
  float* ys = (float*)(base + 163840);

  const int tid = threadIdx.x, lane = tid & 31, wid = tid >> 5;
  const int wm = wid & 1, wn = wid >> 1;
  const int pix0 = blockIdx.x * 128;

  const uint4* Aq = (const uint4*)A2;
  for (int idx = tid; idx < 8192; idx += 256) {
    int ch = idx >> 10, row = (idx >> 3) & 127, c = idx & 7;
    *(uint4*)(base + ch * 16384 + SW128((uint32_t)(row * 128 + c * 16))) =
        Aq[(size_t)(pix0 + row) * 64 + ch * 8 + c];
  }

  const uint4* Bq = (const uint4*)B2;
  const int total = (mode ? 2 : 6) * 12;

  auto prefetchB = [&](int q) {
    int kc2 = q % 12, term = kc2 >> 2;
    int n0g = (q / 12) << 7;
    int b8 = ((term == 1) ? 32 : 0) + (kc2 & 3) * 8;
    uint32_t buf = Bs_a0 + (uint32_t)((q & 1) << 14);
    for (int idx = tid; idx < 1024; idx += 256) {
      int row = idx >> 3, c = idx & 7;
      cp16(buf + SW128((uint32_t)(row * 128 + c * 16)),
           &Bq[(size_t)(n0g + row) * 64 + b8 + c]);
    }
    CP_COMMIT();
  };

  float acc[4][4][4];
#pragma unroll
  for (int i = 0; i < 4; i++)
#pragma unroll
    for (int j = 0; j < 4; j++)
#pragma unroll
      for (int r = 0; r < 4; r++) acc[i][j][r] = 0.f;

  prefetchB(0);

  const int arow_off = (lane & 7) + ((lane >> 3) & 1) * 8;
  const int ak_ex = ((lane >> 4) & 1) * 16;
  const int brow_off = (lane & 7) + ((lane >> 4) & 1) * 8;
  const int bk_ex = ((lane >> 3) & 1) * 16;

  for (int q = 0; q < total; ++q) {
    CP_WAIT0();          // chunk q complete (only group outstanding)
    __syncthreads();     // visible to all; all warps past chunk q-1 reads
    if (q + 1 < total) prefetchB(q + 1);

    const int kc2 = q % 12, term = kc2 >> 2;
    const uint32_t Ab = As_a + (uint32_t)((((term == 2) ? 4 : 0) + (kc2 & 3)) * 16384);
    const uint32_t Bb = Bs_a0 + (uint32_t)((q & 1) << 14);

#pragma unroll
    for (int s = 0; s < 4; ++s) {
      uint32_t af[4][4];
#pragma unroll
      for (int i = 0; i < 4; ++i) {
        uint32_t off = (uint32_t)((wm * 64 + i * 16 + arow_off) * 128 + s * 32 + ak_ex);
        ldsm4(af[i][0], af[i][1], af[i][2], af[i][3], Ab + SW128(off));
      }
      uint32_t bf[4][2];
#pragma unroll
      for (int j2 = 0; j2 < 2; ++j2) {
        uint32_t off = (uint32_t)((wn * 32 + j2 * 16 + brow_off) * 128 + s * 32 + bk_ex);
        ldsm4(bf[2 * j2][0], bf[2 * j2][1], bf[2 * j2 + 1][0], bf[2 * j2 + 1][1],
              Bb + SW128(off));
      }
#pragma unroll
      for (int i = 0; i < 4; ++i)
#pragma unroll
        for (int j = 0; j < 4; ++j) mma16816(acc[i][j], af[i], bf[j]);
    }

    if (kc2 == 11) {
      const int nc = q / 12;
      if (mode == 0) {
        float* dst = (nc < 2) ? g_q : (nc < 4) ? g_k : g_v;
        const int colb = (nc & 1) * 128 + wn * 32;
#pragma unroll
        for (int i = 0; i < 4; ++i) {
          int row0 = pix0 + wm * 64 + i * 16 + (lane >> 2);
#pragma unroll
          for (int j = 0; j < 4; ++j) {
            int col = colb + j * 8 + 2 * (lane & 3);
            *(float2*)(dst + (size_t)row0 * 256 + col) =
                make_float2(acc[i][j][0], acc[i][j][1]);
            *(float2*)(dst + (size_t)(row0 + 8) * 256 + col) =
                make_float2(acc[i][j][2], acc[i][j][3]);
          }
        }
      } else {
        const int t = pix0 >> 16, h = (pix0 >> 8) & 255, w0 = pix0 & 255;
        float* yb = y + (size_t)t * 16777216 + h * 256 + w0;
        for (int g = 0; g < 4; ++g) {
          if (wn == g) {
#pragma unroll
            for (int i = 0; i < 4; ++i) {
              int row0 = wm * 64 + i * 16 + (lane >> 2);
#pragma unroll
              for (int j = 0; j < 4; ++j) {
                int cl = j * 8 + 2 * (lane & 3);
                ys[cl * 132 + row0] = acc[i][j][0];
                ys[(cl + 1) * 132 + row0] = acc[i][j][1];
                ys[cl * 132 + row0 + 8] = acc[i][j][2];
                ys[(cl + 1) * 132 + row0 + 8] = acc[i][j][3];
              }
            }
          }
          __syncthreads();
          const int chb = nc * 128 + g * 32;
          for (int idx = tid; idx < 4096; idx += 256) {
            int cl = idx >> 7, p = idx & 127;
            yb[(size_t)(chb + cl) * 65536 + p] = ys[cl * 132 + p];
          }
          __syncthreads();
        }
      }
#pragma unroll
      for (int i = 0; i < 4; i++)
#pragma unroll
        for (int j = 0; j < 4; j++)
#pragma unroll
          for (int r = 0; r < 4; r++) acc[i][j][r] = 0.f;
    }
  }
}

// ---------------------------------------------------------------------------
// Tiled attention: block = 8(w) x 4(h) pixels, 256 threads (8 warps),
// halo 8x12 cells x 256ch (96KB) + logits/simdot (~16.3KB) = ~112.3KB
// -> 2 independent blocks per SM. cp.async pipelining as in R7.
// Warp = (r = wid&3, seg = wid>>2 in {0,1}); lane8 = 8 channels, hgrp = head.
// ---------------------------------------------------------------------------
__device__ __forceinline__ uint32_t packbf2(float a, float b) {
  __nv_bfloat162 h = __floats2bfloat162_rn(a, b);
  return *reinterpret_cast<uint32_t*>(&h);
}

__global__ void __launch_bounds__(256, 2) attn_kernel(const float* __restrict__ sims) {
  extern __shared__ float sm[];
  float* hs = sm;             // 24576 fl: halo 96 cells x 256 ch
  float* ls = sm + 24576;     // 3328 fl: logits/wts [32][4][26]
  float* sd = ls + 3328;      // 832 fl: simdot [32][26]
  float* ss = ls;             // sims halo [9][96] overlaid on ls (dead before logits)

  const int tid = threadIdx.x, lane = tid & 31, wid = tid >> 5;
  const int bw = blockIdx.x & 31;
  const int bh = (blockIdx.x >> 5) & 63;
  const int t = blockIdx.x >> 11;
  const int w0 = bw << 3, h0 = bh << 2;
  const uint32_t hs_a = smem_u32(hs);

  const int r = wid & 3, seg = wid >> 2;
  const int hgrp = lane >> 3;
  const size_t pixg0 = (size_t)((t << 16) | ((h0 + r) << 8) | (w0 + (seg << 2)));

  // q register loads issued before anything else (hide LDG under halo issue)
  const float4* qg = (const float4*)g_q;
  float4 qa[4], qb[4];
#pragma unroll
  for (int p = 0; p < 4; ++p) {
    qa[p] = qg[(pixg0 + p) * 64 + lane * 2];
    qb[p] = qg[(pixg0 + p) * 64 + lane * 2 + 1];
  }

  // async halo load: 96 cells x 1KB; 24 cp16 per thread
  auto halo_async = [&](const float* src) {
    const char* s = (const char*)src;
#pragma unroll 1
    for (int i = tid; i < 6144; i += 256) {
      int cell = i >> 6, c4 = i & 63;
      int rr = cell / 12, cc = cell - rr * 12;
      int gh = min(max(h0 - 2 + rr, 0), 255);
      int gw = min(max(w0 - 2 + cc, 0), 255);
      cp16(hs_a + (uint32_t)(cell * 1024 + c4 * 16),
           s + ((size_t)((t << 16) | (gh << 8) | gw) * 64 + c4) * 16);
    }
    CP_COMMIT();
  };

  // ---- P0: k halo async || sims halo + simdot ----
  halo_async(g_k);
  for (int i = tid; i < 864; i += 256) {
    int s = i / 96, cell = i - s * 96;
    int rr = cell / 12, cc = cell - rr * 12;
    int gh = min(max(h0 - 2 + rr, 0), 255);
    int gw = min(max(w0 - 2 + cc, 0), 255);
    ss[i] = sims[(size_t)(((t * 9 + s) << 16) | (gh << 8) | gw)];
  }
  __syncthreads();  // ss visible
  for (int i = tid; i < 800; i += 256) {
    int px = i / 25, tap = i - px * 25;
    int rp = px >> 3, wp = px & 7;
    int di = tap / 5, dj = tap - di * 5;
    int ctr = (rp + 2) * 12 + wp + 2;
    int nbc = (rp + di) * 12 + wp + dj;
    float acc = 0.f;
#pragma unroll
    for (int s = 0; s < 9; ++s) acc += ss[s * 96 + ctr] * ss[s * 96 + nbc];
    sd[px * 26 + tap] = acc;
  }
  CP_WAIT0();
  __syncthreads();  // k halo + sd visible; ss region now reusable as ls

  // ---- P1: logits ----
#pragma unroll 1
  for (int di = 0; di < 5; ++di) {
#pragma unroll
    for (int j = 0; j < 8; ++j) {
      const float4* kr = (const float4*)(hs + ((r + di) * 12 + (seg << 2) + j) * 256);
      float4 ka = kr[lane * 2], kb = kr[lane * 2 + 1];
      const int plo = (j - 4 > 0) ? j - 4 : 0;
      const int phi = (j < 3) ? j : 3;
#pragma unroll
      for (int p = plo; p <= phi; ++p) {
        float d = qa[p].x * ka.x + qa[p].y * ka.y + qa[p].z * ka.z + qa[p].w * ka.w +
                  qb[p].x * kb.x + qb[p].y * kb.y + qb[p].z * kb.z + qb[p].w * kb.w;
        d += __shfl_xor_sync(0xffffffffu, d, 1);
        d += __shfl_xor_sync(0xffffffffu, d, 2);
        d += __shfl_xor_sync(0xffffffffu, d, 4);
        if ((lane & 7) == 0) {
          int px = (r << 3) + (seg << 2) + p;
          ls[(px * 4 + hgrp) * 26 + di * 5 + j - p] = d;
        }
      }
    }
  }
  __syncthreads();  // all warps done reading k halo; ls complete

  // ---- P2: v halo async || softmax + sim reweight (in place in ls) ----
  halo_async(g_v);
#pragma unroll 1
  for (int p = 0; p < 4; ++p) {
    const int px = (r << 3) + (seg << 2) + p;
#pragma unroll 1
    for (int h4 = 0; h4 < 4; ++h4) {
      float a = (lane < 25) ? ls[(px * 4 + h4) * 26 + lane] : -1e30f;
      float mx = a;
      mx = fmaxf(mx, __shfl_xor_sync(0xffffffffu, mx, 16));
      mx = fmaxf(mx, __shfl_xor_sync(0xffffffffu, mx, 8));
      mx = fmaxf(mx, __shfl_xor_sync(0xffffffffu, mx, 4));
      mx = fmaxf(mx, __shfl_xor_sync(0xffffffffu, mx, 2));
      mx = fmaxf(mx, __shfl_xor_sync(0xffffffffu, mx, 1));
      float e = (lane < 25) ? __expf(a - mx) * sd[px * 26 + lane] : 0.f;
      float s = e;
      s += __shfl_xor_sync(0xffffffffu, s, 16);
      s += __shfl_xor_sync(0xffffffffu, s, 8);
      s += __shfl_xor_sync(0xffffffffu, s, 4);
      s += __shfl_xor_sync(0xffffffffu, s, 2);
      s += __shfl_xor_sync(0xffffffffu, s, 1);
      if (lane < 25) ls[(px * 4 + h4) * 26 + lane] = e / (1e-10f + s);
    }
  }
  CP_WAIT0();
  __syncthreads();  // v halo + wts visible

  // ---- P3: weighted accumulate ----
  float acc[4][8];
#pragma unroll
  for (int p = 0; p < 4; ++p)
#pragma unroll
    for (int c = 0; c < 8; ++c) acc[p][c] = 0.f;

#pragma unroll 1
  for (int di = 0; di < 5; ++di) {
#pragma unroll
    for (int j = 0; j < 8; ++j) {
      const float4* vr = (const float4*)(hs + ((r + di) * 12 + (seg << 2) + j) * 256);
      float4 va = vr[lane * 2], vb = vr[lane * 2 + 1];
      const int plo = (j - 4 > 0) ? j - 4 : 0;
      const int phi = (j < 3) ? j : 3;
#pragma unroll
      for (int p = plo; p <= phi; ++p) {
        int px = (r << 3) + (seg << 2) + p;
        float wt = ls[(px * 4 + hgrp) * 26 + di * 5 + j - p];
        acc[p][0] += wt * va.x; acc[p][1] += wt * va.y;
        acc[p][2] += wt * va.z; acc[p][3] += wt * va.w;
        acc[p][4] += wt * vb.x; acc[p][5] += wt * vb.y;
        acc[p][6] += wt * vb.z; acc[p][7] += wt * vb.w;
      }
    }
  }

  // ---- store g_o2 bf16 hi|lo directly ----
  uint4* oq = (uint4*)g_o2;
#pragma unroll
  for (int p = 0; p < 4; ++p) {
    float hi[8], lo[8];
#pragma unroll
    for (int c = 0; c < 8; ++c) {
      hi[c] = __bfloat162float(__float2bfloat16_rn(acc[p][c]));
      lo[c] = acc[p][c] - hi[c];
    }
    uint4 hv, lv;
    hv.x = packbf2(hi[0], hi[1]); hv.y = packbf2(hi[2], hi[3]);
    hv.z = packbf2(hi[4], hi[5]); hv.w = packbf2(hi[6], hi[7]);
    lv.x = packbf2(lo[0], lo[1]); lv.y = packbf2(lo[2], lo[3]);
    lv.z = packbf2(lo[4], lo[5]); lv.w = packbf2(lo[6], lo[7]);
    oq[(pixg0 + p) * 64 + lane] = hv;
    oq[(pixg0 + p) * 64 + 32 + lane] = lv;
  }
}

// ---------------------------------------------------------------------------
extern "C" void kernel_launch(void* const* d_in, const int* in_sizes, int n_in,
                              void* d_out, int out_size) {
  (void)in_sizes; (void)n_in; (void)out_size;
  const float* x = (const float*)d_in[0];
  const float* sims = (const float*)d_in[1];
  const float* Wq = (const float*)d_in[3];
  const float* Wk = (const float*)d_in[4];
  const float* Wv = (const float*)d_in[5];
  const float* Wp = (const float*)d_in[6];
  float* out = (float*)d_out;

  const int smem_cx = 256 * 65 * sizeof(float);
  const int smem_gm = 1024 + 163840 + 16896;
  const int smem_at = 28736 * sizeof(float);  // 114944 B -> 2 blocks/SM
  cudaFuncSetAttribute(conv_x, cudaFuncAttributeMaxDynamicSharedMemorySize, smem_cx);
  cudaFuncSetAttribute(gemm_kernel, cudaFuncAttributeMaxDynamicSharedMemorySize, smem_gm);
  cudaFuncSetAttribute(attn_kernel, cudaFuncAttributeMaxDynamicSharedMemorySize, smem_at);

  __nv_bfloat16 *px2, *po2, *pw1, *pw2;
  cudaGetSymbolAddress((void**)&px2, g_x2);
  cudaGetSymbolAddress((void**)&po2, g_o2);
  cudaGetSymbolAddress((void**)&pw1, g_w1);
  cudaGetSymbolAddress((void**)&pw2, g_w2);

  conv_x<<<NPIX / 64, 256, smem_cx>>>(x);
  conv_w<<<1024, 256>>>(Wq, Wk, Wv, Wp);
  gemm_kernel<<<NPIX / 128, 256, smem_gm>>>(px2, pw1, nullptr, 0);
  attn_kernel<<<8192, 256, smem_at>>>(sims);
  gemm_kernel<<<NPIX / 128, 256, smem_gm>>>(po2, pw2, out, 1);
}

// round 12
// speedup vs baseline: 1.1239x; 1.0194x over previous
#include <cuda_runtime.h>
#include <cuda_bf16.h>
#include <cstdint>

// ---------------------------------------------------------------------------
// SuperpixelAttention GB300 — Round 11: M=64 gemm tiles (2 blocks/SM) to
// overlap A-stage/sync/epilogue overheads across blocks. Attn unchanged (R10).
// ---------------------------------------------------------------------------

#define NPIX 262144
#define NELEM 67108864

__device__ float g_q[NELEM];
__device__ float g_k[NELEM];
__device__ float g_v[NELEM];
__device__ __nv_bfloat16 g_x2[NPIX * 512];
__device__ __nv_bfloat16 g_o2[NPIX * 512];
__device__ __nv_bfloat16 g_w1[768 * 512];
__device__ __nv_bfloat16 g_w2[256 * 512];

__device__ __forceinline__ uint32_t smem_u32(const void* p) {
  uint32_t a;
  asm("{ .reg .u64 t; cvta.to.shared.u64 t, %1; cvt.u32.u64 %0, t; }"
      : "=r"(a) : "l"(p));
  return a;
}
#define SW128(o) ((o) ^ (((o) >> 3) & 0x70))

__device__ __forceinline__ void ldsm4(uint32_t& r0, uint32_t& r1, uint32_t& r2,
                                      uint32_t& r3, uint32_t a) {
  asm volatile("ldmatrix.sync.aligned.m8n8.x4.shared.b16 {%0,%1,%2,%3}, [%4];"
               : "=r"(r0), "=r"(r1), "=r"(r2), "=r"(r3) : "r"(a));
}
__device__ __forceinline__ void mma16816(float* c, const uint32_t* a,
                                         const uint32_t* b) {
  asm volatile(
      "mma.sync.aligned.m16n8k16.row.col.f32.bf16.bf16.f32 "
      "{%0,%1,%2,%3},{%4,%5,%6,%7},{%8,%9},{%0,%1,%2,%3};"
      : "+f"(c[0]), "+f"(c[1]), "+f"(c[2]), "+f"(c[3])
      : "r"(a[0]), "r"(a[1]), "r"(a[2]), "r"(a[3]), "r"(b[0]), "r"(b[1]));
}
__device__ __forceinline__ void cp16(uint32_t s, const void* g) {
  asm volatile("cp.async.cg.shared.global [%0], [%1], 16;" :: "r"(s), "l"(g));
}
#define CP_COMMIT() asm volatile("cp.async.commit_group;" ::: "memory")
#define CP_WAIT0()  asm volatile("cp.async.wait_group 0;" ::: "memory")

// ---------------------------------------------------------------------------
// Conversions
// ---------------------------------------------------------------------------
__global__ void __launch_bounds__(256) conv_x(const float* __restrict__ x) {
  extern __shared__ float xs[];  // 256 * 65
  const int tid = threadIdx.x;
  const int pix0 = blockIdx.x * 64;
  const int t = pix0 >> 16, h = (pix0 >> 8) & 255, w0 = pix0 & 255;
  const size_t base = (size_t)t * 16777216 + h * 256 + w0;
  for (int i = tid; i < 16384; i += 256) {
    int c = i >> 6, p = i & 63;
    xs[c * 65 + p] = x[base + (size_t)c * 65536 + p];
  }
  __syncthreads();
  for (int i = tid; i < 32768; i += 256) {
    int p = i >> 9, kk = i & 511, c = kk & 255;
    float v = xs[c * 65 + p];
    __nv_bfloat16 hi = __float2bfloat16_rn(v);
    __nv_bfloat16 o = (kk < 256) ? hi : __float2bfloat16_rn(v - __bfloat162float(hi));
    g_x2[(size_t)(pix0 + p) * 512 + kk] = o;
  }
}

__global__ void __launch_bounds__(256) conv_w(const float* __restrict__ Wq,
                                              const float* __restrict__ Wk,
                                              const float* __restrict__ Wv,
                                              const float* __restrict__ Wp) {
  const int n = blockIdx.x;   // 0..1023
  const int c = threadIdx.x;
  float v;
  __nv_bfloat16* dst;
  if (n < 768) {
    const float* Wm = (n < 256) ? Wq : ((n < 512) ? Wk : Wv);
    v = Wm[c * 256 + (n & 255)];
    if (n < 256) v *= 0.125f;  // fold hd^-0.5 into Wq
    dst = g_w1 + (size_t)n * 512;
  } else {
    v = Wp[c * 256 + (n & 255)];
    dst = g_w2 + (size_t)(n - 768) * 512;
  }
  __nv_bfloat16 hi = __float2bfloat16_rn(v);
  dst[c] = hi;
  dst[256 + c] = __float2bfloat16_rn(v - __bfloat162float(hi));
}

// ---------------------------------------------------------------------------
// mma.sync GEMM — M=64 pixel tiles, 2 blocks/SM.
// smem: A 8x[64][128B] = 64KB | B ring 2x16KB | ys 8.7KB  (~105.5KB + align)
// 8 warps: warp tile m32 x n32 (wm = wid&1, wn = wid>>1).
// ---------------------------------------------------------------------------
__global__ void __launch_bounds__(256, 2) gemm_kernel(
    const __nv_bfloat16* __restrict__ A2,
    const __nv_bfloat16* __restrict__ B2,
    float* __restrict__ y, int mode) {
  extern __shared__ char dsm[];
  char* base = (char*)((((uintptr_t)dsm) + 1023) & ~(uintptr_t)1023);
  const uint32_t As_a = smem_u32(base);
  const uint32_t Bs_a0 = As_a + 65536u;
  float* ys = (float*)(base + 98304);

  const int tid = threadIdx.x, lane = tid & 31, wid = tid >> 5;
  const int wm = wid & 1, wn = wid >> 1;
  const int pix0 = blockIdx.x * 64;

  // stage A: 8 chunks of [64 rows][128B] with SW128
  const uint4* Aq = (const uint4*)A2;
  for (int idx = tid; idx < 4096; idx += 256) {
    int ch = idx >> 9, row = (idx >> 3) & 63, c = idx & 7;
    *(uint4*)(base + ch * 8192 + SW128((uint32_t)(row * 128 + c * 16))) =
        Aq[(size_t)(pix0 + row) * 64 + ch * 8 + c];
  }

  const uint4* Bq = (const uint4*)B2;
  const int total = (mode ? 2 : 6) * 12;

  auto prefetchB = [&](int q) {
    int kc2 = q % 12, term = kc2 >> 2;
    int n0g = (q / 12) << 7;
    int b8 = ((term == 1) ? 32 : 0) + (kc2 & 3) * 8;
    uint32_t buf = Bs_a0 + (uint32_t)((q & 1) << 14);
    for (int idx = tid; idx < 1024; idx += 256) {
      int row = idx >> 3, c = idx & 7;
      cp16(buf + SW128((uint32_t)(row * 128 + c * 16)),
           &Bq[(size_t)(n0g + row) * 64 + b8 + c]);
    }
    CP_COMMIT();
  };

  float acc[2][4][4];
#pragma unroll
  for (int i = 0; i < 2; i++)
#pragma unroll
    for (int j = 0; j < 4; j++)
#pragma unroll
      for (int r = 0; r < 4; r++) acc[i][j][r] = 0.f;

  prefetchB(0);

  const int arow_off = (lane & 7) + ((lane >> 3) & 1) * 8;
  const int ak_ex = ((lane >> 4) & 1) * 16;
  const int brow_off = (lane & 7) + ((lane >> 4) & 1) * 8;
  const int bk_ex = ((lane >> 3) & 1) * 16;

  for (int q = 0; q < total; ++q) {
    CP_WAIT0();
    __syncthreads();
    if (q + 1 < total) prefetchB(q + 1);

    const int kc2 = q % 12, term = kc2 >> 2;
    const uint32_t Ab = As_a + (uint32_t)((((term == 2) ? 4 : 0) + (kc2 & 3)) * 8192);
    const uint32_t Bb = Bs_a0 + (uint32_t)((q & 1) << 14);

#pragma unroll
    for (int s = 0; s < 4; ++s) {
      uint32_t af[2][4];
#pragma unroll
      for (int i = 0; i < 2; ++i) {
        uint32_t off = (uint32_t)((wm * 32 + i * 16 + arow_off) * 128 + s * 32 + ak_ex);
        ldsm4(af[i][0], af[i][1], af[i][2], af[i][3], Ab + SW128(off));
      }
      uint32_t bf[4][2];
#pragma unroll
      for (int j2 = 0; j2 < 2; ++j2) {
        uint32_t off = (uint32_t)((wn * 32 + j2 * 16 + brow_off) * 128 + s * 32 + bk_ex);
        ldsm4(bf[2 * j2][0], bf[2 * j2][1], bf[2 * j2 + 1][0], bf[2 * j2 + 1][1],
              Bb + SW128(off));
      }
#pragma unroll
      for (int i = 0; i < 2; ++i)
#pragma unroll
        for (int j = 0; j < 4; ++j) mma16816(acc[i][j], af[i], bf[j]);
    }

    if (kc2 == 11) {
      const int nc = q / 12;
      if (mode == 0) {
        float* dst = (nc < 2) ? g_q : (nc < 4) ? g_k : g_v;
        const int colb = (nc & 1) * 128 + wn * 32;
#pragma unroll
        for (int i = 0; i < 2; ++i) {
          int row0 = pix0 + wm * 32 + i * 16 + (lane >> 2);
#pragma unroll
          for (int j = 0; j < 4; ++j) {
            int col = colb + j * 8 + 2 * (lane & 3);
            *(float2*)(dst + (size_t)row0 * 256 + col) =
                make_float2(acc[i][j][0], acc[i][j][1]);
            *(float2*)(dst + (size_t)(row0 + 8) * 256 + col) =
                make_float2(acc[i][j][2], acc[i][j][3]);
          }
        }
      } else {
        const int t = pix0 >> 16, h = (pix0 >> 8) & 255, w0 = pix0 & 255;
        float* yb = y + (size_t)t * 16777216 + h * 256 + w0;
        for (int g = 0; g < 4; ++g) {  // 32 channels per round via ys
          if (wn == g) {
#pragma unroll
            for (int i = 0; i < 2; ++i) {
              int row0 = wm * 32 + i * 16 + (lane >> 2);
#pragma unroll
              for (int j = 0; j < 4; ++j) {
                int cl = j * 8 + 2 * (lane & 3);
                ys[cl * 68 + row0] = acc[i][j][0];
                ys[(cl + 1) * 68 + row0] = acc[i][j][1];
                ys[cl * 68 + row0 + 8] = acc[i][j][2];
                ys[(cl + 1) * 68 + row0 + 8] = acc[i][j][3];
              }
            }
          }
          __syncthreads();
          const int chb = nc * 128 + g * 32;
          for (int idx = tid; idx < 2048; idx += 256) {
            int cl = idx >> 6, p = idx & 63;
            yb[(size_t)(chb + cl) * 65536 + p] = ys[cl * 68 + p];
          }
          __syncthreads();
        }
      }
#pragma unroll
      for (int i = 0; i < 2; i++)
#pragma unroll
        for (int j = 0; j < 4; j++)
#pragma unroll
          for (int r = 0; r < 4; r++) acc[i][j][r] = 0.f;
    }
  }
}

// ---------------------------------------------------------------------------
// Tiled attention (unchanged from R10): 8x4 px, 256 thr, 2 blocks/SM.
// ---------------------------------------------------------------------------
__device__ __forceinline__ uint32_t packbf2(float a, float b) {
  __nv_bfloat162 h = __floats2bfloat162_rn(a, b);
  return *reinterpret_cast<uint32_t*>(&h);
}

__global__ void __launch_bounds__(256, 2) attn_kernel(const float* __restrict__ sims) {
  extern __shared__ float sm[];
  float* hs = sm;             // 24576 fl: halo 96 cells x 256 ch
  float* ls = sm + 24576;     // 3328 fl: logits/wts [32][4][26]
  float* sd = ls + 3328;      // 832 fl: simdot [32][26]
  float* ss = ls;             // sims halo [9][96] overlaid on ls

  const int tid = threadIdx.x, lane = tid & 31, wid = tid >> 5;
  const int bw = blockIdx.x & 31;
  const int bh = (blockIdx.x >> 5) & 63;
  const int t = blockIdx.x >> 11;
  const int w0 = bw << 3, h0 = bh << 2;
  const uint32_t hs_a = smem_u32(hs);

  const int r = wid & 3, seg = wid >> 2;
  const int hgrp = lane >> 3;
  const size_t pixg0 = (size_t)((t << 16) | ((h0 + r) << 8) | (w0 + (seg << 2)));

  const float4* qg = (const float4*)g_q;
  float4 qa[4], qb[4];
#pragma unroll
  for (int p = 0; p < 4; ++p) {
    qa[p] = qg[(pixg0 + p) * 64 + lane * 2];
    qb[p] = qg[(pixg0 + p) * 64 + lane * 2 + 1];
  }

  auto halo_async = [&](const float* src) {
    const char* s = (const char*)src;
#pragma unroll 1
    for (int i = tid; i < 6144; i += 256) {
      int cell = i >> 6, c4 = i & 63;
      int rr = cell / 12, cc = cell - rr * 12;
      int gh = min(max(h0 - 2 + rr, 0), 255);
      int gw = min(max(w0 - 2 + cc, 0), 255);
      cp16(hs_a + (uint32_t)(cell * 1024 + c4 * 16),
           s + ((size_t)((t << 16) | (gh << 8) | gw) * 64 + c4) * 16);
    }
    CP_COMMIT();
  };

  // ---- P0: k halo async || sims halo + simdot ----
  halo_async(g_k);
  for (int i = tid; i < 864; i += 256) {
    int s = i / 96, cell = i - s * 96;
    int rr = cell / 12, cc = cell - rr * 12;
    int gh = min(max(h0 - 2 + rr, 0), 255);
    int gw = min(max(w0 - 2 + cc, 0), 255);
    ss[i] = sims[(size_t)(((t * 9 + s) << 16) | (gh << 8) | gw)];
  }
  __syncthreads();
  for (int i = tid; i < 800; i += 256) {
    int px = i / 25, tap = i - px * 25;
    int rp = px >> 3, wp = px & 7;
    int di = tap / 5, dj = tap - di * 5;
    int ctr = (rp + 2) * 12 + wp + 2;
    int nbc = (rp + di) * 12 + wp + dj;
    float acc = 0.f;
#pragma unroll
    for (int s = 0; s < 9; ++s) acc += ss[s * 96 + ctr] * ss[s * 96 + nbc];
    sd[px * 26 + tap] = acc;
  }
  CP_WAIT0();
  __syncthreads();

  // ---- P1: logits ----
#pragma unroll 1
  for (int di = 0; di < 5; ++di) {
#pragma unroll
    for (int j = 0; j < 8; ++j) {
      const float4* kr = (const float4*)(hs + ((r + di) * 12 + (seg << 2) + j) * 256);
      float4 ka = kr[lane * 2], kb = kr[lane * 2 + 1];
      const int plo = (j - 4 > 0) ? j - 4 : 0;
      const int phi = (j < 3) ? j : 3;
#pragma unroll
      for (int p = plo; p <= phi; ++p) {
        float d = qa[p].x * ka.x + qa[p].y * ka.y + qa[p].z * ka.z + qa[p].w * ka.w +
                  qb[p].x * kb.x + qb[p].y * kb.y + qb[p].z * kb.z + qb[p].w * kb.w;
        d += __shfl_xor_sync(0xffffffffu, d, 1);
        d += __shfl_xor_sync(0xffffffffu, d, 2);
        d += __shfl_xor_sync(0xffffffffu, d, 4);
        if ((lane & 7) == 0) {
          int px = (r << 3) + (seg << 2) + p;
          ls[(px * 4 + hgrp) * 26 + di * 5 + j - p] = d;
        }
      }
    }
  }
  __syncthreads();

  // ---- P2: v halo async || softmax + sim reweight ----
  halo_async(g_v);
#pragma unroll 1
  for (int p = 0; p < 4; ++p) {
    const int px = (r << 3) + (seg << 2) + p;
#pragma unroll 1
    for (int h4 = 0; h4 < 4; ++h4) {
      float a = (lane < 25) ? ls[(px * 4 + h4) * 26 + lane] : -1e30f;
      float mx = a;
      mx = fmaxf(mx, __shfl_xor_sync(0xffffffffu, mx, 16));
      mx = fmaxf(mx, __shfl_xor_sync(0xffffffffu, mx, 8));
      mx = fmaxf(mx, __shfl_xor_sync(0xffffffffu, mx, 4));
      mx = fmaxf(mx, __shfl_xor_sync(0xffffffffu, mx, 2));
      mx = fmaxf(mx, __shfl_xor_sync(0xffffffffu, mx, 1));
      float e = (lane < 25) ? __expf(a - mx) * sd[px * 26 + lane] : 0.f;
      float s = e;
      s += __shfl_xor_sync(0xffffffffu, s, 16);
      s += __shfl_xor_sync(0xffffffffu, s, 8);
      s += __shfl_xor_sync(0xffffffffu, s, 4);
      s += __shfl_xor_sync(0xffffffffu, s, 2);
      s += __shfl_xor_sync(0xffffffffu, s, 1);
      if (lane < 25) ls[(px * 4 + h4) * 26 + lane] = e / (1e-10f + s);
    }
  }
  CP_WAIT0();
  __syncthreads();

  // ---- P3: weighted accumulate ----
  float acc[4][8];
#pragma unroll
  for (int p = 0; p < 4; ++p)
#pragma unroll
    for (int c = 0; c < 8; ++c) acc[p][c] = 0.f;

#pragma unroll 1
  for (int di = 0; di < 5; ++di) {
#pragma unroll
    for (int j = 0; j < 8; ++j) {
      const float4* vr = (const float4*)(hs + ((r + di) * 12 + (seg << 2) + j) * 256);
      float4 va = vr[lane * 2], vb = vr[lane * 2 + 1];
      const int plo = (j - 4 > 0) ? j - 4 : 0;
      const int phi = (j < 3) ? j : 3;
#pragma unroll
      for (int p = plo; p <= phi; ++p) {
        int px = (r << 3) + (seg << 2) + p;
        float wt = ls[(px * 4 + hgrp) * 26 + di * 5 + j - p];
        acc[p][0] += wt * va.x; acc[p][1] += wt * va.y;
        acc[p][2] += wt * va.z; acc[p][3] += wt * va.w;
        acc[p][4] += wt * vb.x; acc[p][5] += wt * vb.y;
        acc[p][6] += wt * vb.z; acc[p][7] += wt * vb.w;
      }
    }
  }

  uint4* oq = (uint4*)g_o2;
#pragma unroll
  for (int p = 0; p < 4; ++p) {
    float hi[8], lo[8];
#pragma unroll
    for (int c = 0; c < 8; ++c) {
      hi[c] = __bfloat162float(__float2bfloat16_rn(acc[p][c]));
      lo[c] = acc[p][c] - hi[c];
    }
    uint4 hv, lv;
    hv.x = packbf2(hi[0], hi[1]); hv.y = packbf2(hi[2], hi[3]);
    hv.z = packbf2(hi[4], hi[5]); hv.w = packbf2(hi[6], hi[7]);
    lv.x = packbf2(lo[0], lo[1]); lv.y = packbf2(lo[2], lo[3]);
    lv.z = packbf2(lo[4], lo[5]); lv.w = packbf2(lo[6], lo[7]);
    oq[(pixg0 + p) * 64 + lane] = hv;
    oq[(pixg0 + p) * 64 + 32 + lane] = lv;
  }
}

// ---------------------------------------------------------------------------
extern "C" void kernel_launch(void* const* d_in, const int* in_sizes, int n_in,
                              void* d_out, int out_size) {
  (void)in_sizes; (void)n_in; (void)out_size;
  const float* x = (const float*)d_in[0];
  const float* sims = (const float*)d_in[1];
  const float* Wq = (const float*)d_in[3];
  const float* Wk = (const float*)d_in[4];
  const float* Wv = (const float*)d_in[5];
  const float* Wp = (const float*)d_in[6];
  float* out = (float*)d_out;

  const int smem_cx = 256 * 65 * sizeof(float);
  const int smem_gm = 1024 + 65536 + 32768 + 8704;  // 108032 -> 2 blocks/SM
  const int smem_at = 28736 * sizeof(float);        // 114944 -> 2 blocks/SM
  cudaFuncSetAttribute(conv_x, cudaFuncAttributeMaxDynamicSharedMemorySize, smem_cx);
  cudaFuncSetAttribute(gemm_kernel, cudaFuncAttributeMaxDynamicSharedMemorySize, smem_gm);
  cudaFuncSetAttribute(attn_kernel, cudaFuncAttributeMaxDynamicSharedMemorySize, smem_at);

  __nv_bfloat16 *px2, *po2, *pw1, *pw2;
  cudaGetSymbolAddress((void**)&px2, g_x2);
  cudaGetSymbolAddress((void**)&po2, g_o2);
  cudaGetSymbolAddress((void**)&pw1, g_w1);
  cudaGetSymbolAddress((void**)&pw2, g_w2);

  conv_x<<<NPIX / 64, 256, smem_cx>>>(x);
  conv_w<<<1024, 256>>>(Wq, Wk, Wv, Wp);
  gemm_kernel<<<NPIX / 64, 256, smem_gm>>>(px2, pw1, nullptr, 0);
  attn_kernel<<<8192, 256, smem_at>>>(sims);
  gemm_kernel<<<NPIX / 64, 256, smem_gm>>>(po2, pw2, out, 1);
}

// round 13
// speedup vs baseline: 1.4668x; 1.3051x over previous
#include <cuda_runtime.h>
#include <cuda_fp16.h>
#include <cstdint>

// ---------------------------------------------------------------------------
// SuperpixelAttention GB300 — Round 12: fp16 2-term split GEMMs
//   A = Ah + Al (exact fp16 pair), B = Bh (single fp16)
//   D = Ah*Bh + Al*Bh   (fp32 accum; error ~= B-rounding ~2.8e-4/gemm)
//   Both terms share one B chunk -> half the B prefetch/sync traffic.
// Attn unchanged from R10/R11 (8x4 tiles, 2 blocks/SM, cp.async pipelined).
// ---------------------------------------------------------------------------

#define NPIX 262144
#define NELEM 67108864

__device__ float g_q[NELEM];
__device__ float g_k[NELEM];
__device__ float g_v[NELEM];
__device__ __half g_x2[NPIX * 512];   // [pix][hi256|lo256]
__device__ __half g_o2[NPIX * 512];
__device__ __half g_w1[768 * 256];    // [n][k] single fp16
__device__ __half g_w2[256 * 256];

__device__ __forceinline__ uint32_t smem_u32(const void* p) {
  uint32_t a;
  asm("{ .reg .u64 t; cvta.to.shared.u64 t, %1; cvt.u32.u64 %0, t; }"
      : "=r"(a) : "l"(p));
  return a;
}
#define SW128(o) ((o) ^ (((o) >> 3) & 0x70))

__device__ __forceinline__ void ldsm4(uint32_t& r0, uint32_t& r1, uint32_t& r2,
                                      uint32_t& r3, uint32_t a) {
  asm volatile("ldmatrix.sync.aligned.m8n8.x4.shared.b16 {%0,%1,%2,%3}, [%4];"
               : "=r"(r0), "=r"(r1), "=r"(r2), "=r"(r3) : "r"(a));
}
__device__ __forceinline__ void mma16816(float* c, const uint32_t* a,
                                         const uint32_t* b) {
  asm volatile(
      "mma.sync.aligned.m16n8k16.row.col.f32.f16.f16.f32 "
      "{%0,%1,%2,%3},{%4,%5,%6,%7},{%8,%9},{%0,%1,%2,%3};"
      : "+f"(c[0]), "+f"(c[1]), "+f"(c[2]), "+f"(c[3])
      : "r"(a[0]), "r"(a[1]), "r"(a[2]), "r"(a[3]), "r"(b[0]), "r"(b[1]));
}
__device__ __forceinline__ void cp16(uint32_t s, const void* g) {
  asm volatile("cp.async.cg.shared.global [%0], [%1], 16;" :: "r"(s), "l"(g));
}
#define CP_COMMIT() asm volatile("cp.async.commit_group;" ::: "memory")
#define CP_WAIT0()  asm volatile("cp.async.wait_group 0;" ::: "memory")

// ---------------------------------------------------------------------------
// Conversions
// ---------------------------------------------------------------------------
__global__ void __launch_bounds__(256) conv_x(const float* __restrict__ x) {
  extern __shared__ float xs[];  // 256 * 65
  const int tid = threadIdx.x;
  const int pix0 = blockIdx.x * 64;
  const int t = pix0 >> 16, h = (pix0 >> 8) & 255, w0 = pix0 & 255;
  const size_t base = (size_t)t * 16777216 + h * 256 + w0;
  for (int i = tid; i < 16384; i += 256) {
    int c = i >> 6, p = i & 63;
    xs[c * 65 + p] = x[base + (size_t)c * 65536 + p];
  }
  __syncthreads();
  for (int i = tid; i < 32768; i += 256) {
    int p = i >> 9, kk = i & 511, c = kk & 255;
    float v = xs[c * 65 + p];
    __half hi = __float2half_rn(v);
    __half o = (kk < 256) ? hi : __float2half_rn(v - __half2float(hi));
    g_x2[(size_t)(pix0 + p) * 512 + kk] = o;
  }
}

__global__ void __launch_bounds__(256) conv_w(const float* __restrict__ Wq,
                                              const float* __restrict__ Wk,
                                              const float* __restrict__ Wv,
                                              const float* __restrict__ Wp) {
  const int n = blockIdx.x;   // 0..1023
  const int c = threadIdx.x;
  if (n < 768) {
    const float* Wm = (n < 256) ? Wq : ((n < 512) ? Wk : Wv);
    float v = Wm[c * 256 + (n & 255)];
    if (n < 256) v *= 0.125f;  // fold hd^-0.5 into Wq
    g_w1[(size_t)n * 256 + c] = __float2half_rn(v);
  } else {
    g_w2[(size_t)(n - 768) * 256 + c] = __float2half_rn(Wp[c * 256 + (n & 255)]);
  }
}

// ---------------------------------------------------------------------------
// fp16 2-term GEMM — M=64 pixel tiles, 2 blocks/SM.
// Outer loop: q = (N-chunk)*4 + ksub. Per q: one B chunk load; mma with A-hi
// chunk ksub and A-lo chunk ksub (chunks 0-3 hi, 4-7 lo in A smem).
// smem: A 8x[64][128B]=64KB | B ring 2x16KB | ys 8.7KB.
// ---------------------------------------------------------------------------
__global__ void __launch_bounds__(256, 2) gemm_kernel(
    const __half* __restrict__ A2,
    const __half* __restrict__ B2,
    float* __restrict__ y, int mode) {
  extern __shared__ char dsm[];
  char* base = (char*)((((uintptr_t)dsm) + 1023) & ~(uintptr_t)1023);
  const uint32_t As_a = smem_u32(base);
  const uint32_t Bs_a0 = As_a + 65536u;
  float* ys = (float*)(base + 98304);

  const int tid = threadIdx.x, lane = tid & 31, wid = tid >> 5;
  const int wm = wid & 1, wn = wid >> 1;
  const int pix0 = blockIdx.x * 64;

  // stage A: 8 chunks of [64 rows][128B] (chunks 0-3 = hi, 4-7 = lo)
  const uint4* Aq = (const uint4*)A2;
  for (int idx = tid; idx < 4096; idx += 256) {
    int ch = idx >> 9, row = (idx >> 3) & 63, c = idx & 7;
    *(uint4*)(base + ch * 8192 + SW128((uint32_t)(row * 128 + c * 16))) =
        Aq[(size_t)(pix0 + row) * 64 + ch * 8 + c];
  }

  const uint4* Bq = (const uint4*)B2;  // B row = 256 fp16 = 32 uint4
  const int total = (mode ? 2 : 6) * 4;

  auto prefetchB = [&](int q) {
    int n0g = (q >> 2) << 7;
    int b8 = (q & 3) * 8;
    uint32_t buf = Bs_a0 + (uint32_t)((q & 1) << 14);
    for (int idx = tid; idx < 1024; idx += 256) {
      int row = idx >> 3, c = idx & 7;
      cp16(buf + SW128((uint32_t)(row * 128 + c * 16)),
           &Bq[(size_t)(n0g + row) * 32 + b8 + c]);
    }
    CP_COMMIT();
  };

  float acc[2][4][4];
#pragma unroll
  for (int i = 0; i < 2; i++)
#pragma unroll
    for (int j = 0; j < 4; j++)
#pragma unroll
      for (int r = 0; r < 4; r++) acc[i][j][r] = 0.f;

  prefetchB(0);

  const int arow_off = (lane & 7) + ((lane >> 3) & 1) * 8;
  const int ak_ex = ((lane >> 4) & 1) * 16;
  const int brow_off = (lane & 7) + ((lane >> 4) & 1) * 8;
  const int bk_ex = ((lane >> 3) & 1) * 16;

  for (int q = 0; q < total; ++q) {
    CP_WAIT0();
    __syncthreads();
    if (q + 1 < total) prefetchB(q + 1);

    const int ksub = q & 3;
    const uint32_t Bb = Bs_a0 + (uint32_t)((q & 1) << 14);

#pragma unroll
    for (int s = 0; s < 4; ++s) {
      uint32_t bf[4][2];
#pragma unroll
      for (int j2 = 0; j2 < 2; ++j2) {
        uint32_t off = (uint32_t)((wn * 32 + j2 * 16 + brow_off) * 128 + s * 32 + bk_ex);
        ldsm4(bf[2 * j2][0], bf[2 * j2][1], bf[2 * j2 + 1][0], bf[2 * j2 + 1][1],
              Bb + SW128(off));
      }
#pragma unroll
      for (int term = 0; term < 2; ++term) {
        const uint32_t Ab = As_a + (uint32_t)((term * 4 + ksub) * 8192);
        uint32_t af[2][4];
#pragma unroll
        for (int i = 0; i < 2; ++i) {
          uint32_t off = (uint32_t)((wm * 32 + i * 16 + arow_off) * 128 + s * 32 + ak_ex);
          ldsm4(af[i][0], af[i][1], af[i][2], af[i][3], Ab + SW128(off));
        }
#pragma unroll
        for (int i = 0; i < 2; ++i)
#pragma unroll
          for (int j = 0; j < 4; ++j) mma16816(acc[i][j], af[i], bf[j]);
      }
    }

    if (ksub == 3) {
      const int nc = q >> 2;
      if (mode == 0) {
        float* dst = (nc < 2) ? g_q : (nc < 4) ? g_k : g_v;
        const int colb = (nc & 1) * 128 + wn * 32;
#pragma unroll
        for (int i = 0; i < 2; ++i) {
          int row0 = pix0 + wm * 32 + i * 16 + (lane >> 2);
#pragma unroll
          for (int j = 0; j < 4; ++j) {
            int col = colb + j * 8 + 2 * (lane & 3);
            *(float2*)(dst + (size_t)row0 * 256 + col) =
                make_float2(acc[i][j][0], acc[i][j][1]);
            *(float2*)(dst + (size_t)(row0 + 8) * 256 + col) =
                make_float2(acc[i][j][2], acc[i][j][3]);
          }
        }
      } else {
        const int t = pix0 >> 16, h = (pix0 >> 8) & 255, w0 = pix0 & 255;
        float* yb = y + (size_t)t * 16777216 + h * 256 + w0;
        for (int g = 0; g < 4; ++g) {
          if (wn == g) {
#pragma unroll
            for (int i = 0; i < 2; ++i) {
              int row0 = wm * 32 + i * 16 + (lane >> 2);
#pragma unroll
              for (int j = 0; j < 4; ++j) {
                int cl = j * 8 + 2 * (lane & 3);
                ys[cl * 68 + row0] = acc[i][j][0];
                ys[(cl + 1) * 68 + row0] = acc[i][j][1];
                ys[cl * 68 + row0 + 8] = acc[i][j][2];
                ys[(cl + 1) * 68 + row0 + 8] = acc[i][j][3];
              }
            }
          }
          __syncthreads();
          const int chb = nc * 128 + g * 32;
          for (int idx = tid; idx < 2048; idx += 256) {
            int cl = idx >> 6, p = idx & 63;
            yb[(size_t)(chb + cl) * 65536 + p] = ys[cl * 68 + p];
          }
          __syncthreads();
        }
      }
#pragma unroll
      for (int i = 0; i < 2; i++)
#pragma unroll
        for (int j = 0; j < 4; j++)
#pragma unroll
          for (int r = 0; r < 4; r++) acc[i][j][r] = 0.f;
    }
  }
}

// ---------------------------------------------------------------------------
// Tiled attention (R10 structure): 8x4 px, 256 thr, 2 blocks/SM.
// ---------------------------------------------------------------------------
__device__ __forceinline__ uint32_t packh2(float a, float b) {
  __half2 h = __floats2half2_rn(a, b);
  return *reinterpret_cast<uint32_t*>(&h);
}

__global__ void __launch_bounds__(256, 2) attn_kernel(const float* __restrict__ sims) {
  extern __shared__ float sm[];
  float* hs = sm;             // 24576 fl: halo 96 cells x 256 ch
  float* ls = sm + 24576;     // 3328 fl: logits/wts [32][4][26]
  float* sd = ls + 3328;      // 832 fl: simdot [32][26]
  float* ss = ls;             // sims halo [9][96] overlaid on ls

  const int tid = threadIdx.x, lane = tid & 31, wid = tid >> 5;
  const int bw = blockIdx.x & 31;
  const int bh = (blockIdx.x >> 5) & 63;
  const int t = blockIdx.x >> 11;
  const int w0 = bw << 3, h0 = bh << 2;
  const uint32_t hs_a = smem_u32(hs);

  const int r = wid & 3, seg = wid >> 2;
  const int hgrp = lane >> 3;
  const size_t pixg0 = (size_t)((t << 16) | ((h0 + r) << 8) | (w0 + (seg << 2)));

  const float4* qg = (const float4*)g_q;
  float4 qa[4], qb[4];
#pragma unroll
  for (int p = 0; p < 4; ++p) {
    qa[p] = qg[(pixg0 + p) * 64 + lane * 2];
    qb[p] = qg[(pixg0 + p) * 64 + lane * 2 + 1];
  }

  auto halo_async = [&](const float* src) {
    const char* s = (const char*)src;
#pragma unroll 1
    for (int i = tid; i < 6144; i += 256) {
      int cell = i >> 6, c4 = i & 63;
      int rr = cell / 12, cc = cell - rr * 12;
      int gh = min(max(h0 - 2 + rr, 0), 255);
      int gw = min(max(w0 - 2 + cc, 0), 255);
      cp16(hs_a + (uint32_t)(cell * 1024 + c4 * 16),
           s + ((size_t)((t << 16) | (gh << 8) | gw) * 64 + c4) * 16);
    }
    CP_COMMIT();
  };

  // ---- P0: k halo async || sims halo + simdot ----
  halo_async(g_k);
  for (int i = tid; i < 864; i += 256) {
    int s = i / 96, cell = i - s * 96;
    int rr = cell / 12, cc = cell - rr * 12;
    int gh = min(max(h0 - 2 + rr, 0), 255);
    int gw = min(max(w0 - 2 + cc, 0), 255);
    ss[i] = sims[(size_t)(((t * 9 + s) << 16) | (gh << 8) | gw)];
  }
  __syncthreads();
  for (int i = tid; i < 800; i += 256) {
    int px = i / 25, tap = i - px * 25;
    int rp = px >> 3, wp = px & 7;
    int di = tap / 5, dj = tap - di * 5;
    int ctr = (rp + 2) * 12 + wp + 2;
    int nbc = (rp + di) * 12 + wp + dj;
    float acc = 0.f;
#pragma unroll
    for (int s = 0; s < 9; ++s) acc += ss[s * 96 + ctr] * ss[s * 96 + nbc];
    sd[px * 26 + tap] = acc;
  }
  CP_WAIT0();
  __syncthreads();

  // ---- P1: logits ----
#pragma unroll 1
  for (int di = 0; di < 5; ++di) {
#pragma unroll
    for (int j = 0; j < 8; ++j) {
      const float4* kr = (const float4*)(hs + ((r + di) * 12 + (seg << 2) + j) * 256);
      float4 ka = kr[lane * 2], kb = kr[lane * 2 + 1];
      const int plo = (j - 4 > 0) ? j - 4 : 0;
      const int phi = (j < 3) ? j : 3;
#pragma unroll
      for (int p = plo; p <= phi; ++p) {
        float d = qa[p].x * ka.x + qa[p].y * ka.y + qa[p].z * ka.z + qa[p].w * ka.w +
                  qb[p].x * kb.x + qb[p].y * kb.y + qb[p].z * kb.z + qb[p].w * kb.w;
        d += __shfl_xor_sync(0xffffffffu, d, 1);
        d += __shfl_xor_sync(0xffffffffu, d, 2);
        d += __shfl_xor_sync(0xffffffffu, d, 4);
        if ((lane & 7) == 0) {
          int px = (r << 3) + (seg << 2) + p;
          ls[(px * 4 + hgrp) * 26 + di * 5 + j - p] = d;
        }
      }
    }
  }
  __syncthreads();

  // ---- P2: v halo async || softmax + sim reweight ----
  halo_async(g_v);
#pragma unroll 1
  for (int p = 0; p < 4; ++p) {
    const int px = (r << 3) + (seg << 2) + p;
#pragma unroll 1
    for (int h4 = 0; h4 < 4; ++h4) {
      float a = (lane < 25) ? ls[(px * 4 + h4) * 26 + lane] : -1e30f;
      float mx = a;
      mx = fmaxf(mx, __shfl_xor_sync(0xffffffffu, mx, 16));
      mx = fmaxf(mx, __shfl_xor_sync(0xffffffffu, mx, 8));
      mx = fmaxf(mx, __shfl_xor_sync(0xffffffffu, mx, 4));
      mx = fmaxf(mx, __shfl_xor_sync(0xffffffffu, mx, 2));
      mx = fmaxf(mx, __shfl_xor_sync(0xffffffffu, mx, 1));
      float e = (lane < 25) ? __expf(a - mx) * sd[px * 26 + lane] : 0.f;
      float s = e;
      s += __shfl_xor_sync(0xffffffffu, s, 16);
      s += __shfl_xor_sync(0xffffffffu, s, 8);
      s += __shfl_xor_sync(0xffffffffu, s, 4);
      s += __shfl_xor_sync(0xffffffffu, s, 2);
      s += __shfl_xor_sync(0xffffffffu, s, 1);
      if (lane < 25) ls[(px * 4 + h4) * 26 + lane] = e / (1e-10f + s);
    }
  }
  CP_WAIT0();
  __syncthreads();

  // ---- P3: weighted accumulate ----
  float acc[4][8];
#pragma unroll
  for (int p = 0; p < 4; ++p)
#pragma unroll
    for (int c = 0; c < 8; ++c) acc[p][c] = 0.f;

#pragma unroll 1
  for (int di = 0; di < 5; ++di) {
#pragma unroll
    for (int j = 0; j < 8; ++j) {
      const float4* vr = (const float4*)(hs + ((r + di) * 12 + (seg << 2) + j) * 256);
      float4 va = vr[lane * 2], vb = vr[lane * 2 + 1];
      const int plo = (j - 4 > 0) ? j - 4 : 0;
      const int phi = (j < 3) ? j : 3;
#pragma unroll
      for (int p = plo; p <= phi; ++p) {
        int px = (r << 3) + (seg << 2) + p;
        float wt = ls[(px * 4 + hgrp) * 26 + di * 5 + j - p];
        acc[p][0] += wt * va.x; acc[p][1] += wt * va.y;
        acc[p][2] += wt * va.z; acc[p][3] += wt * va.w;
        acc[p][4] += wt * vb.x; acc[p][5] += wt * vb.y;
        acc[p][6] += wt * vb.z; acc[p][7] += wt * vb.w;
      }
    }
  }

  // ---- store g_o2 fp16 hi|lo directly ----
  uint4* oq = (uint4*)g_o2;
#pragma unroll
  for (int p = 0; p < 4; ++p) {
    float hi[8], lo[8];
#pragma unroll
    for (int c = 0; c < 8; ++c) {
      hi[c] = __half2float(__float2half_rn(acc[p][c]));
      lo[c] = acc[p][c] - hi[c];
    }
    uint4 hv, lv;
    hv.x = packh2(hi[0], hi[1]); hv.y = packh2(hi[2], hi[3]);
    hv.z = packh2(hi[4], hi[5]); hv.w = packh2(hi[6], hi[7]);
    lv.x = packh2(lo[0], lo[1]); lv.y = packh2(lo[2], lo[3]);
    lv.z = packh2(lo[4], lo[5]); lv.w = packh2(lo[6], lo[7]);
    oq[(pixg0 + p) * 64 + lane] = hv;
    oq[(pixg0 + p) * 64 + 32 + lane] = lv;
  }
}

// ---------------------------------------------------------------------------
extern "C" void kernel_launch(void* const* d_in, const int* in_sizes, int n_in,
                              void* d_out, int out_size) {
  (void)in_sizes; (void)n_in; (void)out_size;
  const float* x = (const float*)d_in[0];
  const float* sims = (const float*)d_in[1];
  const float* Wq = (const float*)d_in[3];
  const float* Wk = (const float*)d_in[4];
  const float* Wv = (const float*)d_in[5];
  const float* Wp = (const float*)d_in[6];
  float* out = (float*)d_out;

  const int smem_cx = 256 * 65 * sizeof(float);
  const int smem_gm = 1024 + 65536 + 32768 + 8704;  // 108032 -> 2 blocks/SM
  const int smem_at = 28736 * sizeof(float);        // 114944 -> 2 blocks/SM
  cudaFuncSetAttribute(conv_x, cudaFuncAttributeMaxDynamicSharedMemorySize, smem_cx);
  cudaFuncSetAttribute(gemm_kernel, cudaFuncAttributeMaxDynamicSharedMemorySize, smem_gm);
  cudaFuncSetAttribute(attn_kernel, cudaFuncAttributeMaxDynamicSharedMemorySize, smem_at);

  __half *px2, *po2, *pw1, *pw2;
  cudaGetSymbolAddress((void**)&px2, g_x2);
  cudaGetSymbolAddress((void**)&po2, g_o2);
  cudaGetSymbolAddress((void**)&pw1, g_w1);
  cudaGetSymbolAddress((void**)&pw2, g_w2);

  conv_x<<<NPIX / 64, 256, smem_cx>>>(x);
  conv_w<<<1024, 256>>>(Wq, Wk, Wv, Wp);
  gemm_kernel<<<NPIX / 64, 256, smem_gm>>>(px2, pw1, nullptr, 0);
  attn_kernel<<<8192, 256, smem_at>>>(sims);
  gemm_kernel<<<NPIX / 64, 256, smem_gm>>>(po2, pw2, out, 1);
}

// round 14
// speedup vs baseline: 1.7706x; 1.2071x over previous
#include <cuda_runtime.h>
#include <cuda_fp16.h>
#include <cstdint>

// ---------------------------------------------------------------------------
// SuperpixelAttention GB300 — Round 13: fp16 k/v end-to-end.
//   gemm(0) writes q fp32, k/v fp16 -> attn halo bytes halve (48KB smem,
//   3 blocks/SM). fp16 2-term split GEMMs unchanged from R12.
// ---------------------------------------------------------------------------

#define NPIX 262144
#define NELEM 67108864

__device__ float g_q[NELEM];
__device__ __half g_k2[NPIX * 256];
__device__ __half g_v2[NPIX * 256];
__device__ __half g_x2[NPIX * 512];   // [pix][hi256|lo256]
__device__ __half g_o2[NPIX * 512];
__device__ __half g_w1[768 * 256];    // [n][k] single fp16
__device__ __half g_w2[256 * 256];

__device__ __forceinline__ uint32_t smem_u32(const void* p) {
  uint32_t a;
  asm("{ .reg .u64 t; cvta.to.shared.u64 t, %1; cvt.u32.u64 %0, t; }"
      : "=r"(a) : "l"(p));
  return a;
}
#define SW128(o) ((o) ^ (((o) >> 3) & 0x70))

__device__ __forceinline__ void ldsm4(uint32_t& r0, uint32_t& r1, uint32_t& r2,
                                      uint32_t& r3, uint32_t a) {
  asm volatile("ldmatrix.sync.aligned.m8n8.x4.shared.b16 {%0,%1,%2,%3}, [%4];"
               : "=r"(r0), "=r"(r1), "=r"(r2), "=r"(r3) : "r"(a));
}
__device__ __forceinline__ void mma16816(float* c, const uint32_t* a,
                                         const uint32_t* b) {
  asm volatile(
      "mma.sync.aligned.m16n8k16.row.col.f32.f16.f16.f32 "
      "{%0,%1,%2,%3},{%4,%5,%6,%7},{%8,%9},{%0,%1,%2,%3};"
      : "+f"(c[0]), "+f"(c[1]), "+f"(c[2]), "+f"(c[3])
      : "r"(a[0]), "r"(a[1]), "r"(a[2]), "r"(a[3]), "r"(b[0]), "r"(b[1]));
}
__device__ __forceinline__ void cp16(uint32_t s, const void* g) {
  asm volatile("cp.async.cg.shared.global [%0], [%1], 16;" :: "r"(s), "l"(g));
}
#define CP_COMMIT() asm volatile("cp.async.commit_group;" ::: "memory")
#define CP_WAIT0()  asm volatile("cp.async.wait_group 0;" ::: "memory")

__device__ __forceinline__ uint32_t packh2(float a, float b) {
  __half2 h = __floats2half2_rn(a, b);
  return *reinterpret_cast<uint32_t*>(&h);
}

// ---------------------------------------------------------------------------
// Conversions
// ---------------------------------------------------------------------------
__global__ void __launch_bounds__(256) conv_x(const float* __restrict__ x) {
  extern __shared__ float xs[];  // 256 * 65
  const int tid = threadIdx.x;
  const int pix0 = blockIdx.x * 64;
  const int t = pix0 >> 16, h = (pix0 >> 8) & 255, w0 = pix0 & 255;
  const size_t base = (size_t)t * 16777216 + h * 256 + w0;
  for (int i = tid; i < 16384; i += 256) {
    int c = i >> 6, p = i & 63;
    xs[c * 65 + p] = x[base + (size_t)c * 65536 + p];
  }
  __syncthreads();
  for (int i = tid; i < 32768; i += 256) {
    int p = i >> 9, kk = i & 511, c = kk & 255;
    float v = xs[c * 65 + p];
    __half hi = __float2half_rn(v);
    __half o = (kk < 256) ? hi : __float2half_rn(v - __half2float(hi));
    g_x2[(size_t)(pix0 + p) * 512 + kk] = o;
  }
}

__global__ void __launch_bounds__(256) conv_w(const float* __restrict__ Wq,
                                              const float* __restrict__ Wk,
                                              const float* __restrict__ Wv,
                                              const float* __restrict__ Wp) {
  const int n = blockIdx.x;   // 0..1023
  const int c = threadIdx.x;
  if (n < 768) {
    const float* Wm = (n < 256) ? Wq : ((n < 512) ? Wk : Wv);
    float v = Wm[c * 256 + (n & 255)];
    if (n < 256) v *= 0.125f;  // fold hd^-0.5 into Wq
    g_w1[(size_t)n * 256 + c] = __float2half_rn(v);
  } else {
    g_w2[(size_t)(n - 768) * 256 + c] = __float2half_rn(Wp[c * 256 + (n & 255)]);
  }
}

// ---------------------------------------------------------------------------
// fp16 2-term GEMM — M=64 pixel tiles, 2 blocks/SM (unchanged from R12,
// except mode-0 epilogue writes k/v as fp16).
// ---------------------------------------------------------------------------
__global__ void __launch_bounds__(256, 2) gemm_kernel(
    const __half* __restrict__ A2,
    const __half* __restrict__ B2,
    float* __restrict__ y, int mode) {
  extern __shared__ char dsm[];
  char* base = (char*)((((uintptr_t)dsm) + 1023) & ~(uintptr_t)1023);
  const uint32_t As_a = smem_u32(base);
  const uint32_t Bs_a0 = As_a + 65536u;
  float* ys = (float*)(base + 98304);

  const int tid = threadIdx.x, lane = tid & 31, wid = tid >> 5;
  const int wm = wid & 1, wn = wid >> 1;
  const int pix0 = blockIdx.x * 64;

  const uint4* Aq = (const uint4*)A2;
  for (int idx = tid; idx < 4096; idx += 256) {
    int ch = idx >> 9, row = (idx >> 3) & 63, c = idx & 7;
    *(uint4*)(base + ch * 8192 + SW128((uint32_t)(row * 128 + c * 16))) =
        Aq[(size_t)(pix0 + row) * 64 + ch * 8 + c];
  }

  const uint4* Bq = (const uint4*)B2;
  const int total = (mode ? 2 : 6) * 4;

  auto prefetchB = [&](int q) {
    int n0g = (q >> 2) << 7;
    int b8 = (q & 3) * 8;
    uint32_t buf = Bs_a0 + (uint32_t)((q & 1) << 14);
    for (int idx = tid; idx < 1024; idx += 256) {
      int row = idx >> 3, c = idx & 7;
      cp16(buf + SW128((uint32_t)(row * 128 + c * 16)),
           &Bq[(size_t)(n0g + row) * 32 + b8 + c]);
    }
    CP_COMMIT();
  };

  float acc[2][4][4];
#pragma unroll
  for (int i = 0; i < 2; i++)
#pragma unroll
    for (int j = 0; j < 4; j++)
#pragma unroll
      for (int r = 0; r < 4; r++) acc[i][j][r] = 0.f;

  prefetchB(0);

  const int arow_off = (lane & 7) + ((lane >> 3) & 1) * 8;
  const int ak_ex = ((lane >> 4) & 1) * 16;
  const int brow_off = (lane & 7) + ((lane >> 4) & 1) * 8;
  const int bk_ex = ((lane >> 3) & 1) * 16;

  for (int q = 0; q < total; ++q) {
    CP_WAIT0();
    __syncthreads();
    if (q + 1 < total) prefetchB(q + 1);

    const int ksub = q & 3;
    const uint32_t Bb = Bs_a0 + (uint32_t)((q & 1) << 14);

#pragma unroll
    for (int s = 0; s < 4; ++s) {
      uint32_t bf[4][2];
#pragma unroll
      for (int j2 = 0; j2 < 2; ++j2) {
        uint32_t off = (uint32_t)((wn * 32 + j2 * 16 + brow_off) * 128 + s * 32 + bk_ex);
        ldsm4(bf[2 * j2][0], bf[2 * j2][1], bf[2 * j2 + 1][0], bf[2 * j2 + 1][1],
              Bb + SW128(off));
      }
#pragma unroll
      for (int term = 0; term < 2; ++term) {
        const uint32_t Ab = As_a + (uint32_t)((term * 4 + ksub) * 8192);
        uint32_t af[2][4];
#pragma unroll
        for (int i = 0; i < 2; ++i) {
          uint32_t off = (uint32_t)((wm * 32 + i * 16 + arow_off) * 128 + s * 32 + ak_ex);
          ldsm4(af[i][0], af[i][1], af[i][2], af[i][3], Ab + SW128(off));
        }
#pragma unroll
        for (int i = 0; i < 2; ++i)
#pragma unroll
          for (int j = 0; j < 4; ++j) mma16816(acc[i][j], af[i], bf[j]);
      }
    }

    if (ksub == 3) {
      const int nc = q >> 2;
      if (mode == 0) {
        const int colb = (nc & 1) * 128 + wn * 32;
        if (nc < 2) {  // q: fp32
#pragma unroll
          for (int i = 0; i < 2; ++i) {
            int row0 = pix0 + wm * 32 + i * 16 + (lane >> 2);
#pragma unroll
            for (int j = 0; j < 4; ++j) {
              int col = colb + j * 8 + 2 * (lane & 3);
              *(float2*)(g_q + (size_t)row0 * 256 + col) =
                  make_float2(acc[i][j][0], acc[i][j][1]);
              *(float2*)(g_q + (size_t)(row0 + 8) * 256 + col) =
                  make_float2(acc[i][j][2], acc[i][j][3]);
            }
          }
        } else {       // k/v: fp16
          uint32_t* dst = (uint32_t*)((nc < 4) ? g_k2 : g_v2);
#pragma unroll
          for (int i = 0; i < 2; ++i) {
            int row0 = pix0 + wm * 32 + i * 16 + (lane >> 2);
#pragma unroll
            for (int j = 0; j < 4; ++j) {
              int col = colb + j * 8 + 2 * (lane & 3);
              dst[((size_t)row0 * 256 + col) >> 1] = packh2(acc[i][j][0], acc[i][j][1]);
              dst[((size_t)(row0 + 8) * 256 + col) >> 1] = packh2(acc[i][j][2], acc[i][j][3]);
            }
          }
        }
      } else {
        const int t = pix0 >> 16, h = (pix0 >> 8) & 255, w0 = pix0 & 255;
        float* yb = y + (size_t)t * 16777216 + h * 256 + w0;
        for (int g = 0; g < 4; ++g) {
          if (wn == g) {
#pragma unroll
            for (int i = 0; i < 2; ++i) {
              int row0 = wm * 32 + i * 16 + (lane >> 2);
#pragma unroll
              for (int j = 0; j < 4; ++j) {
                int cl = j * 8 + 2 * (lane & 3);
                ys[cl * 68 + row0] = acc[i][j][0];
                ys[(cl + 1) * 68 + row0] = acc[i][j][1];
                ys[cl * 68 + row0 + 8] = acc[i][j][2];
                ys[(cl + 1) * 68 + row0 + 8] = acc[i][j][3];
              }
            }
          }
          __syncthreads();
          const int chb = nc * 128 + g * 32;
          for (int idx = tid; idx < 2048; idx += 256) {
            int cl = idx >> 6, p = idx & 63;
            yb[(size_t)(chb + cl) * 65536 + p] = ys[cl * 68 + p];
          }
          __syncthreads();
        }
      }
#pragma unroll
      for (int i = 0; i < 2; i++)
#pragma unroll
        for (int j = 0; j < 4; j++)
#pragma unroll
          for (int r = 0; r < 4; r++) acc[i][j][r] = 0.f;
    }
  }
}

// ---------------------------------------------------------------------------
// Tiled attention: 8x4 px, 256 thr; fp16 halo (48KB) -> ~66KB smem,
// 3 blocks/SM. Structure identical to R12 otherwise.
// smem bytes: halo 49152 | ls 13312 (fp32, sims halo overlaid) | sd 3328
// ---------------------------------------------------------------------------
__global__ void __launch_bounds__(256, 3) attn_kernel(const float* __restrict__ sims) {
  extern __shared__ char smc[];
  char* hsc = smc;                          // 49152 B: halo 96 cells x 256 ch fp16
  float* ls = (float*)(smc + 49152);        // 3328 fl
  float* sd = (float*)(smc + 62464);        // 832 fl
  float* ss = ls;                           // sims halo [9][96] overlay

  const int tid = threadIdx.x, lane = tid & 31, wid = tid >> 5;
  const int bw = blockIdx.x & 31;
  const int bh = (blockIdx.x >> 5) & 63;
  const int t = blockIdx.x >> 11;
  const int w0 = bw << 3, h0 = bh << 2;
  const uint32_t hs_a = smem_u32(hsc);

  const int r = wid & 3, seg = wid >> 2;
  const int hgrp = lane >> 3;
  const size_t pixg0 = (size_t)((t << 16) | ((h0 + r) << 8) | (w0 + (seg << 2)));

  const float4* qg = (const float4*)g_q;
  float4 qa[4], qb[4];
#pragma unroll
  for (int p = 0; p < 4; ++p) {
    qa[p] = qg[(pixg0 + p) * 64 + lane * 2];
    qb[p] = qg[(pixg0 + p) * 64 + lane * 2 + 1];
  }

  // async halo load: 96 cells x 512B; 12 cp16 per thread
  auto halo_async = [&](const __half* src) {
    const char* s = (const char*)src;
#pragma unroll 1
    for (int i = tid; i < 3072; i += 256) {
      int cell = i >> 5, c4 = i & 31;
      int rr = cell / 12, cc = cell - rr * 12;
      int gh = min(max(h0 - 2 + rr, 0), 255);
      int gw = min(max(w0 - 2 + cc, 0), 255);
      cp16(hs_a + (uint32_t)(cell * 512 + c4 * 16),
           s + (size_t)((t << 16) | (gh << 8) | gw) * 512 + c4 * 16);
    }
    CP_COMMIT();
  };

  // ---- P0: k halo async || sims halo + simdot ----
  halo_async(g_k2);
  for (int i = tid; i < 864; i += 256) {
    int s = i / 96, cell = i - s * 96;
    int rr = cell / 12, cc = cell - rr * 12;
    int gh = min(max(h0 - 2 + rr, 0), 255);
    int gw = min(max(w0 - 2 + cc, 0), 255);
    ss[i] = sims[(size_t)(((t * 9 + s) << 16) | (gh << 8) | gw)];
  }
  __syncthreads();
  for (int i = tid; i < 800; i += 256) {
    int px = i / 25, tap = i - px * 25;
    int rp = px >> 3, wp = px & 7;
    int di = tap / 5, dj = tap - di * 5;
    int ctr = (rp + 2) * 12 + wp + 2;
    int nbc = (rp + di) * 12 + wp + dj;
    float acc = 0.f;
#pragma unroll
    for (int s = 0; s < 9; ++s) acc += ss[s * 96 + ctr] * ss[s * 96 + nbc];
    sd[px * 26 + tap] = acc;
  }
  CP_WAIT0();
  __syncthreads();

  // ---- P1: logits ----
#pragma unroll 1
  for (int di = 0; di < 5; ++di) {
#pragma unroll
    for (int j = 0; j < 8; ++j) {
      const uint4 kv = *(const uint4*)(hsc + ((r + di) * 12 + (seg << 2) + j) * 512 +
                                       lane * 16);
      const __half2* kh = (const __half2*)&kv;
      float2 f0 = __half22float2(kh[0]), f1 = __half22float2(kh[1]);
      float2 f2 = __half22float2(kh[2]), f3 = __half22float2(kh[3]);
      const int plo = (j - 4 > 0) ? j - 4 : 0;
      const int phi = (j < 3) ? j : 3;
#pragma unroll
      for (int p = plo; p <= phi; ++p) {
        float d = qa[p].x * f0.x + qa[p].y * f0.y + qa[p].z * f1.x + qa[p].w * f1.y +
                  qb[p].x * f2.x + qb[p].y * f2.y + qb[p].z * f3.x + qb[p].w * f3.y;
        d += __shfl_xor_sync(0xffffffffu, d, 1);
        d += __shfl_xor_sync(0xffffffffu, d, 2);
        d += __shfl_xor_sync(0xffffffffu, d, 4);
        if ((lane & 7) == 0) {
          int px = (r << 3) + (seg << 2) + p;
          ls[(px * 4 + hgrp) * 26 + di * 5 + j - p] = d;
        }
      }
    }
  }
  __syncthreads();

  // ---- P2: v halo async || softmax + sim reweight ----
  halo_async(g_v2);
#pragma unroll 1
  for (int p = 0; p < 4; ++p) {
    const int px = (r << 3) + (seg << 2) + p;
#pragma unroll 1
    for (int h4 = 0; h4 < 4; ++h4) {
      float a = (lane < 25) ? ls[(px * 4 + h4) * 26 + lane] : -1e30f;
      float mx = a;
      mx = fmaxf(mx, __shfl_xor_sync(0xffffffffu, mx, 16));
      mx = fmaxf(mx, __shfl_xor_sync(0xffffffffu, mx, 8));
      mx = fmaxf(mx, __shfl_xor_sync(0xffffffffu, mx, 4));
      mx = fmaxf(mx, __shfl_xor_sync(0xffffffffu, mx, 2));
      mx = fmaxf(mx, __shfl_xor_sync(0xffffffffu, mx, 1));
      float e = (lane < 25) ? __expf(a - mx) * sd[px * 26 + lane] : 0.f;
      float s = e;
      s += __shfl_xor_sync(0xffffffffu, s, 16);
      s += __shfl_xor_sync(0xffffffffu, s, 8);
      s += __shfl_xor_sync(0xffffffffu, s, 4);
      s += __shfl_xor_sync(0xffffffffu, s, 2);
      s += __shfl_xor_sync(0xffffffffu, s, 1);
      if (lane < 25) ls[(px * 4 + h4) * 26 + lane] = e / (1e-10f + s);
    }
  }
  CP_WAIT0();
  __syncthreads();

  // ---- P3: weighted accumulate ----
  float acc[4][8];
#pragma unroll
  for (int p = 0; p < 4; ++p)
#pragma unroll
    for (int c = 0; c < 8; ++c) acc[p][c] = 0.f;

#pragma unroll 1
  for (int di = 0; di < 5; ++di) {
#pragma unroll
    for (int j = 0; j < 8; ++j) {
      const uint4 vv = *(const uint4*)(hsc + ((r + di) * 12 + (seg << 2) + j) * 512 +
                                       lane * 16);
      const __half2* vh = (const __half2*)&vv;
      float2 f0 = __half22float2(vh[0]), f1 = __half22float2(vh[1]);
      float2 f2 = __half22float2(vh[2]), f3 = __half22float2(vh[3]);
      const int plo = (j - 4 > 0) ? j - 4 : 0;
      const int phi = (j < 3) ? j : 3;
#pragma unroll
      for (int p = plo; p <= phi; ++p) {
        int px = (r << 3) + (seg << 2) + p;
        float wt = ls[(px * 4 + hgrp) * 26 + di * 5 + j - p];
        acc[p][0] += wt * f0.x; acc[p][1] += wt * f0.y;
        acc[p][2] += wt * f1.x; acc[p][3] += wt * f1.y;
        acc[p][4] += wt * f2.x; acc[p][5] += wt * f2.y;
        acc[p][6] += wt * f3.x; acc[p][7] += wt * f3.y;
      }
    }
  }

  // ---- store g_o2 fp16 hi|lo directly ----
  uint4* oq = (uint4*)g_o2;
#pragma unroll
  for (int p = 0; p < 4; ++p) {
    float hi[8], lo[8];
#pragma unroll
    for (int c = 0; c < 8; ++c) {
      hi[c] = __half2float(__float2half_rn(acc[p][c]));
      lo[c] = acc[p][c] - hi[c];
    }
    uint4 hv, lv;
    hv.x = packh2(hi[0], hi[1]); hv.y = packh2(hi[2], hi[3]);
    hv.z = packh2(hi[4], hi[5]); hv.w = packh2(hi[6], hi[7]);
    lv.x = packh2(lo[0], lo[1]); lv.y = packh2(lo[2], lo[3]);
    lv.z = packh2(lo[4], lo[5]); lv.w = packh2(lo[6], lo[7]);
    oq[(pixg0 + p) * 64 + lane] = hv;
    oq[(pixg0 + p) * 64 + 32 + lane] = lv;
  }
}

// ---------------------------------------------------------------------------
extern "C" void kernel_launch(void* const* d_in, const int* in_sizes, int n_in,
                              void* d_out, int out_size) {
  (void)in_sizes; (void)n_in; (void)out_size;
  const float* x = (const float*)d_in[0];
  const float* sims = (const float*)d_in[1];
  const float* Wq = (const float*)d_in[3];
  const float* Wk = (const float*)d_in[4];
  const float* Wv = (const float*)d_in[5];
  const float* Wp = (const float*)d_in[6];
  float* out = (float*)d_out;

  const int smem_cx = 256 * 65 * sizeof(float);
  const int smem_gm = 1024 + 65536 + 32768 + 8704;  // 108032 -> 2 blocks/SM
  const int smem_at = 65792;                        // 48K halo + ls + sd -> 3 blocks/SM
  cudaFuncSetAttribute(conv_x, cudaFuncAttributeMaxDynamicSharedMemorySize, smem_cx);
  cudaFuncSetAttribute(gemm_kernel, cudaFuncAttributeMaxDynamicSharedMemorySize, smem_gm);
  cudaFuncSetAttribute(attn_kernel, cudaFuncAttributeMaxDynamicSharedMemorySize, smem_at);

  __half *px2, *po2, *pw1, *pw2;
  cudaGetSymbolAddress((void**)&px2, g_x2);
  cudaGetSymbolAddress((void**)&po2, g_o2);
  cudaGetSymbolAddress((void**)&pw1, g_w1);
  cudaGetSymbolAddress((void**)&pw2, g_w2);

  conv_x<<<NPIX / 64, 256, smem_cx>>>(x);
  conv_w<<<1024, 256>>>(Wq, Wk, Wv, Wp);
  gemm_kernel<<<NPIX / 64, 256, smem_gm>>>(px2, pw1, nullptr, 0);
  attn_kernel<<<8192, 256, smem_at>>>(sims);
  gemm_kernel<<<NPIX / 64, 256, smem_gm>>>(po2, pw2, out, 1);
}

// round 15
// speedup vs baseline: 2.0535x; 1.1598x over previous
#include <cuda_runtime.h>
#include <cuda_fp16.h>
#include <cstdint>

// ---------------------------------------------------------------------------
// SuperpixelAttention GB300 — Round 14: single-term gemm0 (q/k/v = fp16 x ·
// fp16 W, one mma term), 2-term gemm1 (proj). fp16 k/v attn from R13.
// ---------------------------------------------------------------------------

#define NPIX 262144

__device__ float g_q[NPIX * 256];
__device__ __half g_k2[NPIX * 256];
__device__ __half g_v2[NPIX * 256];
__device__ __half g_x2[NPIX * 512];   // [pix][hi256|lo256] (lo unused, kept for layout)
__device__ __half g_o2[NPIX * 512];
__device__ __half g_w1[768 * 256];    // [n][k] single fp16
__device__ __half g_w2[256 * 256];

__device__ __forceinline__ uint32_t smem_u32(const void* p) {
  uint32_t a;
  asm("{ .reg .u64 t; cvta.to.shared.u64 t, %1; cvt.u32.u64 %0, t; }"
      : "=r"(a) : "l"(p));
  return a;
}
#define SW128(o) ((o) ^ (((o) >> 3) & 0x70))

__device__ __forceinline__ void ldsm4(uint32_t& r0, uint32_t& r1, uint32_t& r2,
                                      uint32_t& r3, uint32_t a) {
  asm volatile("ldmatrix.sync.aligned.m8n8.x4.shared.b16 {%0,%1,%2,%3}, [%4];"
               : "=r"(r0), "=r"(r1), "=r"(r2), "=r"(r3) : "r"(a));
}
__device__ __forceinline__ void mma16816(float* c, const uint32_t* a,
                                         const uint32_t* b) {
  asm volatile(
      "mma.sync.aligned.m16n8k16.row.col.f32.f16.f16.f32 "
      "{%0,%1,%2,%3},{%4,%5,%6,%7},{%8,%9},{%0,%1,%2,%3};"
      : "+f"(c[0]), "+f"(c[1]), "+f"(c[2]), "+f"(c[3])
      : "r"(a[0]), "r"(a[1]), "r"(a[2]), "r"(a[3]), "r"(b[0]), "r"(b[1]));
}
__device__ __forceinline__ void cp16(uint32_t s, const void* g) {
  asm volatile("cp.async.cg.shared.global [%0], [%1], 16;" :: "r"(s), "l"(g));
}
#define CP_COMMIT() asm volatile("cp.async.commit_group;" ::: "memory")
#define CP_WAIT0()  asm volatile("cp.async.wait_group 0;" ::: "memory")

__device__ __forceinline__ uint32_t packh2(float a, float b) {
  __half2 h = __floats2half2_rn(a, b);
  return *reinterpret_cast<uint32_t*>(&h);
}

// ---------------------------------------------------------------------------
// Conversions
// ---------------------------------------------------------------------------
__global__ void __launch_bounds__(256) conv_x(const float* __restrict__ x) {
  extern __shared__ float xs[];  // 256 * 65
  const int tid = threadIdx.x;
  const int pix0 = blockIdx.x * 64;
  const int t = pix0 >> 16, h = (pix0 >> 8) & 255, w0 = pix0 & 255;
  const size_t base = (size_t)t * 16777216 + h * 256 + w0;
  for (int i = tid; i < 16384; i += 256) {
    int c = i >> 6, p = i & 63;
    xs[c * 65 + p] = x[base + (size_t)c * 65536 + p];
  }
  __syncthreads();
  // hi only (gemm0 is single-term)
  for (int i = tid; i < 16384; i += 256) {
    int p = i >> 8, c = i & 255;
    g_x2[(size_t)(pix0 + p) * 512 + c] = __float2half_rn(xs[c * 65 + p]);
  }
}

__global__ void __launch_bounds__(256) conv_w(const float* __restrict__ Wq,
                                              const float* __restrict__ Wk,
                                              const float* __restrict__ Wv,
                                              const float* __restrict__ Wp) {
  const int n = blockIdx.x;   // 0..1023
  const int c = threadIdx.x;
  if (n < 768) {
    const float* Wm = (n < 256) ? Wq : ((n < 512) ? Wk : Wv);
    float v = Wm[c * 256 + (n & 255)];
    if (n < 256) v *= 0.125f;  // fold hd^-0.5 into Wq
    g_w1[(size_t)n * 256 + c] = __float2half_rn(v);
  } else {
    g_w2[(size_t)(n - 768) * 256 + c] = __float2half_rn(Wp[c * 256 + (n & 255)]);
  }
}

// ---------------------------------------------------------------------------
// fp16 GEMM — M=64 pixel tiles, 2 blocks/SM; `terms` selects 1- or 2-term
// split (A chunks 0-3 = hi, 4-7 = lo).
// ---------------------------------------------------------------------------
__global__ void __launch_bounds__(256, 2) gemm_kernel(
    const __half* __restrict__ A2,
    const __half* __restrict__ B2,
    float* __restrict__ y, int mode, int terms) {
  extern __shared__ char dsm[];
  char* base = (char*)((((uintptr_t)dsm) + 1023) & ~(uintptr_t)1023);
  const uint32_t As_a = smem_u32(base);
  const uint32_t Bs_a0 = As_a + 65536u;
  float* ys = (float*)(base + 98304);

  const int tid = threadIdx.x, lane = tid & 31, wid = tid >> 5;
  const int wm = wid & 1, wn = wid >> 1;
  const int pix0 = blockIdx.x * 64;

  // stage A: terms*4 chunks of [64 rows][128B]
  const uint4* Aq = (const uint4*)A2;
  const int astage = terms * 2048;
  for (int idx = tid; idx < astage; idx += 256) {
    int ch = idx >> 9, row = (idx >> 3) & 63, c = idx & 7;
    *(uint4*)(base + ch * 8192 + SW128((uint32_t)(row * 128 + c * 16))) =
        Aq[(size_t)(pix0 + row) * 64 + ch * 8 + c];
  }

  const uint4* Bq = (const uint4*)B2;
  const int total = (mode ? 2 : 6) * 4;

  auto prefetchB = [&](int q) {
    int n0g = (q >> 2) << 7;
    int b8 = (q & 3) * 8;
    uint32_t buf = Bs_a0 + (uint32_t)((q & 1) << 14);
    for (int idx = tid; idx < 1024; idx += 256) {
      int row = idx >> 3, c = idx & 7;
      cp16(buf + SW128((uint32_t)(row * 128 + c * 16)),
           &Bq[(size_t)(n0g + row) * 32 + b8 + c]);
    }
    CP_COMMIT();
  };

  float acc[2][4][4];
#pragma unroll
  for (int i = 0; i < 2; i++)
#pragma unroll
    for (int j = 0; j < 4; j++)
#pragma unroll
      for (int r = 0; r < 4; r++) acc[i][j][r] = 0.f;

  prefetchB(0);

  const int arow_off = (lane & 7) + ((lane >> 3) & 1) * 8;
  const int ak_ex = ((lane >> 4) & 1) * 16;
  const int brow_off = (lane & 7) + ((lane >> 4) & 1) * 8;
  const int bk_ex = ((lane >> 3) & 1) * 16;

  for (int q = 0; q < total; ++q) {
    CP_WAIT0();
    __syncthreads();
    if (q + 1 < total) prefetchB(q + 1);

    const int ksub = q & 3;
    const uint32_t Bb = Bs_a0 + (uint32_t)((q & 1) << 14);

#pragma unroll
    for (int s = 0; s < 4; ++s) {
      uint32_t bf[4][2];
#pragma unroll
      for (int j2 = 0; j2 < 2; ++j2) {
        uint32_t off = (uint32_t)((wn * 32 + j2 * 16 + brow_off) * 128 + s * 32 + bk_ex);
        ldsm4(bf[2 * j2][0], bf[2 * j2][1], bf[2 * j2 + 1][0], bf[2 * j2 + 1][1],
              Bb + SW128(off));
      }
#pragma unroll 2
      for (int term = 0; term < terms; ++term) {
        const uint32_t Ab = As_a + (uint32_t)((term * 4 + ksub) * 8192);
        uint32_t af[2][4];
#pragma unroll
        for (int i = 0; i < 2; ++i) {
          uint32_t off = (uint32_t)((wm * 32 + i * 16 + arow_off) * 128 + s * 32 + ak_ex);
          ldsm4(af[i][0], af[i][1], af[i][2], af[i][3], Ab + SW128(off));
        }
#pragma unroll
        for (int i = 0; i < 2; ++i)
#pragma unroll
          for (int j = 0; j < 4; ++j) mma16816(acc[i][j], af[i], bf[j]);
      }
    }

    if (ksub == 3) {
      const int nc = q >> 2;
      if (mode == 0) {
        const int colb = (nc & 1) * 128 + wn * 32;
        if (nc < 2) {  // q: fp32
#pragma unroll
          for (int i = 0; i < 2; ++i) {
            int row0 = pix0 + wm * 32 + i * 16 + (lane >> 2);
#pragma unroll
            for (int j = 0; j < 4; ++j) {
              int col = colb + j * 8 + 2 * (lane & 3);
              *(float2*)(g_q + (size_t)row0 * 256 + col) =
                  make_float2(acc[i][j][0], acc[i][j][1]);
              *(float2*)(g_q + (size_t)(row0 + 8) * 256 + col) =
                  make_float2(acc[i][j][2], acc[i][j][3]);
            }
          }
        } else {       // k/v: fp16
          uint32_t* dst = (uint32_t*)((nc < 4) ? g_k2 : g_v2);
#pragma unroll
          for (int i = 0; i < 2; ++i) {
            int row0 = pix0 + wm * 32 + i * 16 + (lane >> 2);
#pragma unroll
            for (int j = 0; j < 4; ++j) {
              int col = colb + j * 8 + 2 * (lane & 3);
              dst[((size_t)row0 * 256 + col) >> 1] = packh2(acc[i][j][0], acc[i][j][1]);
              dst[((size_t)(row0 + 8) * 256 + col) >> 1] = packh2(acc[i][j][2], acc[i][j][3]);
            }
          }
        }
      } else {
        const int t = pix0 >> 16, h = (pix0 >> 8) & 255, w0 = pix0 & 255;
        float* yb = y + (size_t)t * 16777216 + h * 256 + w0;
        for (int g = 0; g < 4; ++g) {
          if (wn == g) {
#pragma unroll
            for (int i = 0; i < 2; ++i) {
              int row0 = wm * 32 + i * 16 + (lane >> 2);
#pragma unroll
              for (int j = 0; j < 4; ++j) {
                int cl = j * 8 + 2 * (lane & 3);
                ys[cl * 68 + row0] = acc[i][j][0];
                ys[(cl + 1) * 68 + row0] = acc[i][j][1];
                ys[cl * 68 + row0 + 8] = acc[i][j][2];
                ys[(cl + 1) * 68 + row0 + 8] = acc[i][j][3];
              }
            }
          }
          __syncthreads();
          const int chb = nc * 128 + g * 32;
          for (int idx = tid; idx < 2048; idx += 256) {
            int cl = idx >> 6, p = idx & 63;
            yb[(size_t)(chb + cl) * 65536 + p] = ys[cl * 68 + p];
          }
          __syncthreads();
        }
      }
#pragma unroll
      for (int i = 0; i < 2; i++)
#pragma unroll
        for (int j = 0; j < 4; j++)
#pragma unroll
          for (int r = 0; r < 4; r++) acc[i][j][r] = 0.f;
    }
  }
}

// ---------------------------------------------------------------------------
// Tiled attention (R13): 8x4 px, 256 thr, fp16 halo 48KB, 3 blocks/SM.
// ---------------------------------------------------------------------------
__global__ void __launch_bounds__(256, 3) attn_kernel(const float* __restrict__ sims) {
  extern __shared__ char smc[];
  char* hsc = smc;                          // 49152 B: halo 96 cells x 256 ch fp16
  float* ls = (float*)(smc + 49152);        // 3328 fl
  float* sd = (float*)(smc + 62464);        // 832 fl
  float* ss = ls;                           // sims halo [9][96] overlay

  const int tid = threadIdx.x, lane = tid & 31, wid = tid >> 5;
  const int bw = blockIdx.x & 31;
  const int bh = (blockIdx.x >> 5) & 63;
  const int t = blockIdx.x >> 11;
  const int w0 = bw << 3, h0 = bh << 2;
  const uint32_t hs_a = smem_u32(hsc);

  const int r = wid & 3, seg = wid >> 2;
  const int hgrp = lane >> 3;
  const size_t pixg0 = (size_t)((t << 16) | ((h0 + r) << 8) | (w0 + (seg << 2)));

  const float4* qg = (const float4*)g_q;
  float4 qa[4], qb[4];
#pragma unroll
  for (int p = 0; p < 4; ++p) {
    qa[p] = qg[(pixg0 + p) * 64 + lane * 2];
    qb[p] = qg[(pixg0 + p) * 64 + lane * 2 + 1];
  }

  auto halo_async = [&](const __half* src) {
    const char* s = (const char*)src;
#pragma unroll 1
    for (int i = tid; i < 3072; i += 256) {
      int cell = i >> 5, c4 = i & 31;
      int rr = cell / 12, cc = cell - rr * 12;
      int gh = min(max(h0 - 2 + rr, 0), 255);
      int gw = min(max(w0 - 2 + cc, 0), 255);
      cp16(hs_a + (uint32_t)(cell * 512 + c4 * 16),
           s + (size_t)((t << 16) | (gh << 8) | gw) * 512 + c4 * 16);
    }
    CP_COMMIT();
  };

  // ---- P0: k halo async || sims halo + simdot ----
  halo_async(g_k2);
  for (int i = tid; i < 864; i += 256) {
    int s = i / 96, cell = i - s * 96;
    int rr = cell / 12, cc = cell - rr * 12;
    int gh = min(max(h0 - 2 + rr, 0), 255);
    int gw = min(max(w0 - 2 + cc, 0), 255);
    ss[i] = sims[(size_t)(((t * 9 + s) << 16) | (gh << 8) | gw)];
  }
  __syncthreads();
  for (int i = tid; i < 800; i += 256) {
    int px = i / 25, tap = i - px * 25;
    int rp = px >> 3, wp = px & 7;
    int di = tap / 5, dj = tap - di * 5;
    int ctr = (rp + 2) * 12 + wp + 2;
    int nbc = (rp + di) * 12 + wp + dj;
    float acc = 0.f;
#pragma unroll
    for (int s = 0; s < 9; ++s) acc += ss[s * 96 + ctr] * ss[s * 96 + nbc];
    sd[px * 26 + tap] = acc;
  }
  CP_WAIT0();
  __syncthreads();

  // ---- P1: logits ----
#pragma unroll 1
  for (int di = 0; di < 5; ++di) {
#pragma unroll
    for (int j = 0; j < 8; ++j) {
      const uint4 kv = *(const uint4*)(hsc + ((r + di) * 12 + (seg << 2) + j) * 512 +
                                       lane * 16);
      const __half2* kh = (const __half2*)&kv;
      float2 f0 = __half22float2(kh[0]), f1 = __half22float2(kh[1]);
      float2 f2 = __half22float2(kh[2]), f3 = __half22float2(kh[3]);
      const int plo = (j - 4 > 0) ? j - 4 : 0;
      const int phi = (j < 3) ? j : 3;
#pragma unroll
      for (int p = plo; p <= phi; ++p) {
        float d = qa[p].x * f0.x + qa[p].y * f0.y + qa[p].z * f1.x + qa[p].w * f1.y +
                  qb[p].x * f2.x + qb[p].y * f2.y + qb[p].z * f3.x + qb[p].w * f3.y;
        d += __shfl_xor_sync(0xffffffffu, d, 1);
        d += __shfl_xor_sync(0xffffffffu, d, 2);
        d += __shfl_xor_sync(0xffffffffu, d, 4);
        if ((lane & 7) == 0) {
          int px = (r << 3) + (seg << 2) + p;
          ls[(px * 4 + hgrp) * 26 + di * 5 + j - p] = d;
        }
      }
    }
  }
  __syncthreads();

  // ---- P2: v halo async || softmax + sim reweight ----
  halo_async(g_v2);
#pragma unroll 1
  for (int p = 0; p < 4; ++p) {
    const int px = (r << 3) + (seg << 2) + p;
#pragma unroll 1
    for (int h4 = 0; h4 < 4; ++h4) {
      float a = (lane < 25) ? ls[(px * 4 + h4) * 26 + lane] : -1e30f;
      float mx = a;
      mx = fmaxf(mx, __shfl_xor_sync(0xffffffffu, mx, 16));
      mx = fmaxf(mx, __shfl_xor_sync(0xffffffffu, mx, 8));
      mx = fmaxf(mx, __shfl_xor_sync(0xffffffffu, mx, 4));
      mx = fmaxf(mx, __shfl_xor_sync(0xffffffffu, mx, 2));
      mx = fmaxf(mx, __shfl_xor_sync(0xffffffffu, mx, 1));
      float e = (lane < 25) ? __expf(a - mx) * sd[px * 26 + lane] : 0.f;
      float s = e;
      s += __shfl_xor_sync(0xffffffffu, s, 16);
      s += __shfl_xor_sync(0xffffffffu, s, 8);
      s += __shfl_xor_sync(0xffffffffu, s, 4);
      s += __shfl_xor_sync(0xffffffffu, s, 2);
      s += __shfl_xor_sync(0xffffffffu, s, 1);
      if (lane < 25) ls[(px * 4 + h4) * 26 + lane] = e / (1e-10f + s);
    }
  }
  CP_WAIT0();
  __syncthreads();

  // ---- P3: weighted accumulate ----
  float acc[4][8];
#pragma unroll
  for (int p = 0; p < 4; ++p)
#pragma unroll
    for (int c = 0; c < 8; ++c) acc[p][c] = 0.f;

#pragma unroll 1
  for (int di = 0; di < 5; ++di) {
#pragma unroll
    for (int j = 0; j < 8; ++j) {
      const uint4 vv = *(const uint4*)(hsc + ((r + di) * 12 + (seg << 2) + j) * 512 +
                                       lane * 16);
      const __half2* vh = (const __half2*)&vv;
      float2 f0 = __half22float2(vh[0]), f1 = __half22float2(vh[1]);
      float2 f2 = __half22float2(vh[2]), f3 = __half22float2(vh[3]);
      const int plo = (j - 4 > 0) ? j - 4 : 0;
      const int phi = (j < 3) ? j : 3;
#pragma unroll
      for (int p = plo; p <= phi; ++p) {
        int px = (r << 3) + (seg << 2) + p;
        float wt = ls[(px * 4 + hgrp) * 26 + di * 5 + j - p];
        acc[p][0] += wt * f0.x; acc[p][1] += wt * f0.y;
        acc[p][2] += wt * f1.x; acc[p][3] += wt * f1.y;
        acc[p][4] += wt * f2.x; acc[p][5] += wt * f2.y;
        acc[p][6] += wt * f3.x; acc[p][7] += wt * f3.y;
      }
    }
  }

  // ---- store g_o2 fp16 hi|lo directly ----
  uint4* oq = (uint4*)g_o2;
#pragma unroll
  for (int p = 0; p < 4; ++p) {
    float hi[8], lo[8];
#pragma unroll
    for (int c = 0; c < 8; ++c) {
      hi[c] = __half2float(__float2half_rn(acc[p][c]));
      lo[c] = acc[p][c] - hi[c];
    }
    uint4 hv, lv;
    hv.x = packh2(hi[0], hi[1]); hv.y = packh2(hi[2], hi[3]);
    hv.z = packh2(hi[4], hi[5]); hv.w = packh2(hi[6], hi[7]);
    lv.x = packh2(lo[0], lo[1]); lv.y = packh2(lo[2], lo[3]);
    lv.z = packh2(lo[4], lo[5]); lv.w = packh2(lo[6], lo[7]);
    oq[(pixg0 + p) * 64 + lane] = hv;
    oq[(pixg0 + p) * 64 + 32 + lane] = lv;
  }
}

// ---------------------------------------------------------------------------
extern "C" void kernel_launch(void* const* d_in, const int* in_sizes, int n_in,
                              void* d_out, int out_size) {
  (void)in_sizes; (void)n_in; (void)out_size;
  const float* x = (const float*)d_in[0];
  const float* sims = (const float*)d_in[1];
  const float* Wq = (const float*)d_in[3];
  const float* Wk = (const float*)d_in[4];
  const float* Wv = (const float*)d_in[5];
  const float* Wp = (const float*)d_in[6];
  float* out = (float*)d_out;

  const int smem_cx = 256 * 65 * sizeof(float);
  const int smem_gm = 1024 + 65536 + 32768 + 8704;  // 108032 -> 2 blocks/SM
  const int smem_at = 65792;                        // -> 3 blocks/SM
  cudaFuncSetAttribute(conv_x, cudaFuncAttributeMaxDynamicSharedMemorySize, smem_cx);
  cudaFuncSetAttribute(gemm_kernel, cudaFuncAttributeMaxDynamicSharedMemorySize, smem_gm);
  cudaFuncSetAttribute(attn_kernel, cudaFuncAttributeMaxDynamicSharedMemorySize, smem_at);

  __half *px2, *po2, *pw1, *pw2;
  cudaGetSymbolAddress((void**)&px2, g_x2);
  cudaGetSymbolAddress((void**)&po2, g_o2);
  cudaGetSymbolAddress((void**)&pw1, g_w1);
  cudaGetSymbolAddress((void**)&pw2, g_w2);

  conv_x<<<NPIX / 64, 256, smem_cx>>>(x);
  conv_w<<<1024, 256>>>(Wq, Wk, Wv, Wp);
  gemm_kernel<<<NPIX / 64, 256, smem_gm>>>(px2, pw1, nullptr, 0, 1);
  attn_kernel<<<8192, 256, smem_at>>>(sims);
  gemm_kernel<<<NPIX / 64, 256, smem_gm>>>(po2, pw2, out, 1, 2);
}

// round 16
// speedup vs baseline: 2.5967x; 1.2645x over previous
#include <cuda_runtime.h>
#include <cuda_fp16.h>
#include <cstdint>

// ---------------------------------------------------------------------------
// SuperpixelAttention GB300 — Round 15:
//   * conv_x fused into gemm0 A-stage (reads x fp32 directly, cvt in-kernel)
//   * gemm1 single-term (o2 plain fp16 [pix][256]); attn epilogue plain fp16
//   * both gemms single-term -> 73.5KB smem -> 3 blocks/SM
// Attn unchanged from R13/R14 (fp16 halo, 3 blocks/SM).
// ---------------------------------------------------------------------------

#define NPIX 262144

__device__ float g_q[NPIX * 256];
__device__ __half g_k2[NPIX * 256];
__device__ __half g_v2[NPIX * 256];
__device__ __half g_o2[NPIX * 256];
__device__ __half g_w1[768 * 256];    // [n][k] fp16 (q scale folded)
__device__ __half g_w2[256 * 256];

__device__ __forceinline__ uint32_t smem_u32(const void* p) {
  uint32_t a;
  asm("{ .reg .u64 t; cvta.to.shared.u64 t, %1; cvt.u32.u64 %0, t; }"
      : "=r"(a) : "l"(p));
  return a;
}
#define SW128(o) ((o) ^ (((o) >> 3) & 0x70))

__device__ __forceinline__ void ldsm4(uint32_t& r0, uint32_t& r1, uint32_t& r2,
                                      uint32_t& r3, uint32_t a) {
  asm volatile("ldmatrix.sync.aligned.m8n8.x4.shared.b16 {%0,%1,%2,%3}, [%4];"
               : "=r"(r0), "=r"(r1), "=r"(r2), "=r"(r3) : "r"(a));
}
__device__ __forceinline__ void mma16816(float* c, const uint32_t* a,
                                         const uint32_t* b) {
  asm volatile(
      "mma.sync.aligned.m16n8k16.row.col.f32.f16.f16.f32 "
      "{%0,%1,%2,%3},{%4,%5,%6,%7},{%8,%9},{%0,%1,%2,%3};"
      : "+f"(c[0]), "+f"(c[1]), "+f"(c[2]), "+f"(c[3])
      : "r"(a[0]), "r"(a[1]), "r"(a[2]), "r"(a[3]), "r"(b[0]), "r"(b[1]));
}
__device__ __forceinline__ void cp16(uint32_t s, const void* g) {
  asm volatile("cp.async.cg.shared.global [%0], [%1], 16;" :: "r"(s), "l"(g));
}
#define CP_COMMIT() asm volatile("cp.async.commit_group;" ::: "memory")
#define CP_WAIT0()  asm volatile("cp.async.wait_group 0;" ::: "memory")

__device__ __forceinline__ uint32_t packh2(float a, float b) {
  __half2 h = __floats2half2_rn(a, b);
  return *reinterpret_cast<uint32_t*>(&h);
}

// ---------------------------------------------------------------------------
// conv_w: weights -> fp16 (q scale folded into Wq)
// ---------------------------------------------------------------------------
__global__ void __launch_bounds__(256) conv_w(const float* __restrict__ Wq,
                                              const float* __restrict__ Wk,
                                              const float* __restrict__ Wv,
                                              const float* __restrict__ Wp) {
  const int n = blockIdx.x;   // 0..1023
  const int c = threadIdx.x;
  if (n < 768) {
    const float* Wm = (n < 256) ? Wq : ((n < 512) ? Wk : Wv);
    float v = Wm[c * 256 + (n & 255)];
    if (n < 256) v *= 0.125f;
    g_w1[(size_t)n * 256 + c] = __float2half_rn(v);
  } else {
    g_w2[(size_t)(n - 768) * 256 + c] = __float2half_rn(Wp[c * 256 + (n & 255)]);
  }
}

// ---------------------------------------------------------------------------
// fp16 single-term GEMM — M=64 pixel tiles, 3 blocks/SM.
// mode 0: A = x fp32 [T,C,H,W] (transposed+converted during staging), B=g_w1,
//         6 N-chunks -> q fp32 | k,v fp16.
// mode 1: A = g_o2 fp16 [pix][256], B=g_w2, 2 N-chunks -> y (transposed store).
// smem: A 4x8KB | B ring 2x16KB | ys 8.7KB  (~73.5KB)
// ---------------------------------------------------------------------------
__global__ void __launch_bounds__(256, 3) gemm_kernel(
    const void* __restrict__ Ain,
    const __half* __restrict__ B2,
    float* __restrict__ y, int mode) {
  extern __shared__ char dsm[];
  char* base = (char*)((((uintptr_t)dsm) + 1023) & ~(uintptr_t)1023);
  const uint32_t As_a = smem_u32(base);
  const uint32_t Bs_a0 = As_a + 32768u;
  float* ys = (float*)(base + 65536);

  const int tid = threadIdx.x, lane = tid & 31, wid = tid >> 5;
  const int wm = wid & 1, wn = wid >> 1;
  const int pix0 = blockIdx.x * 64;

  // ---- stage A: 4 chunks of [64 rows][128B] (SW128) ----
  if (mode == 0) {
    // x fp32, channel-major: transpose + convert. half2 stores (2 ch/store).
    const float* xf = (const float*)Ain;
    const int t = pix0 >> 16, h = (pix0 >> 8) & 255, w0 = pix0 & 255;
    const size_t gb = (size_t)t * 16777216 + h * 256 + w0;
#pragma unroll 4
    for (int idx = tid; idx < 8192; idx += 256) {
      int ce = (idx >> 6) << 1;      // even channel 0..254
      int row = idx & 63;            // pixel within tile (coalesced along w)
      float f0 = xf[gb + (size_t)ce * 65536 + row];
      float f1 = xf[gb + (size_t)(ce + 1) * 65536 + row];
      int chunk = ce >> 6, cc = ce & 63;
      uint32_t addr = (uint32_t)(chunk * 8192) +
                      SW128((uint32_t)(row * 128 + (cc >> 3) * 16)) + (cc & 7) * 2;
      *(uint32_t*)(base + addr) = packh2(f0, f1);
    }
  } else {
    const uint4* Aq = (const uint4*)Ain;  // [pix][256] half = 32 uint4/pix
    for (int idx = tid; idx < 2048; idx += 256) {
      int ch = idx >> 9, row = (idx >> 3) & 63, c = idx & 7;
      *(uint4*)(base + ch * 8192 + SW128((uint32_t)(row * 128 + c * 16))) =
          Aq[(size_t)(pix0 + row) * 32 + ch * 8 + c];
    }
  }

  const uint4* Bq = (const uint4*)B2;   // [n][256] half = 32 uint4/row
  const int total = (mode ? 2 : 6) * 4;

  auto prefetchB = [&](int q) {
    int n0g = (q >> 2) << 7;
    int b8 = (q & 3) * 8;
    uint32_t buf = Bs_a0 + (uint32_t)((q & 1) << 14);
    for (int idx = tid; idx < 1024; idx += 256) {
      int row = idx >> 3, c = idx & 7;
      cp16(buf + SW128((uint32_t)(row * 128 + c * 16)),
           &Bq[(size_t)(n0g + row) * 32 + b8 + c]);
    }
    CP_COMMIT();
  };

  float acc[2][4][4];
#pragma unroll
  for (int i = 0; i < 2; i++)
#pragma unroll
    for (int j = 0; j < 4; j++)
#pragma unroll
      for (int r = 0; r < 4; r++) acc[i][j][r] = 0.f;

  prefetchB(0);

  const int arow_off = (lane & 7) + ((lane >> 3) & 1) * 8;
  const int ak_ex = ((lane >> 4) & 1) * 16;
  const int brow_off = (lane & 7) + ((lane >> 4) & 1) * 8;
  const int bk_ex = ((lane >> 3) & 1) * 16;

  for (int q = 0; q < total; ++q) {
    CP_WAIT0();
    __syncthreads();
    if (q + 1 < total) prefetchB(q + 1);

    const int ksub = q & 3;
    const uint32_t Ab = As_a + (uint32_t)(ksub * 8192);
    const uint32_t Bb = Bs_a0 + (uint32_t)((q & 1) << 14);

#pragma unroll
    for (int s = 0; s < 4; ++s) {
      uint32_t bf[4][2];
#pragma unroll
      for (int j2 = 0; j2 < 2; ++j2) {
        uint32_t off = (uint32_t)((wn * 32 + j2 * 16 + brow_off) * 128 + s * 32 + bk_ex);
        ldsm4(bf[2 * j2][0], bf[2 * j2][1], bf[2 * j2 + 1][0], bf[2 * j2 + 1][1],
              Bb + SW128(off));
      }
      uint32_t af[2][4];
#pragma unroll
      for (int i = 0; i < 2; ++i) {
        uint32_t off = (uint32_t)((wm * 32 + i * 16 + arow_off) * 128 + s * 32 + ak_ex);
        ldsm4(af[i][0], af[i][1], af[i][2], af[i][3], Ab + SW128(off));
      }
#pragma unroll
      for (int i = 0; i < 2; ++i)
#pragma unroll
        for (int j = 0; j < 4; ++j) mma16816(acc[i][j], af[i], bf[j]);
    }

    if (ksub == 3) {
      const int nc = q >> 2;
      if (mode == 0) {
        const int colb = (nc & 1) * 128 + wn * 32;
        if (nc < 2) {  // q: fp32
#pragma unroll
          for (int i = 0; i < 2; ++i) {
            int row0 = pix0 + wm * 32 + i * 16 + (lane >> 2);
#pragma unroll
            for (int j = 0; j < 4; ++j) {
              int col = colb + j * 8 + 2 * (lane & 3);
              *(float2*)(g_q + (size_t)row0 * 256 + col) =
                  make_float2(acc[i][j][0], acc[i][j][1]);
              *(float2*)(g_q + (size_t)(row0 + 8) * 256 + col) =
                  make_float2(acc[i][j][2], acc[i][j][3]);
            }
          }
        } else {       // k/v: fp16
          uint32_t* dst = (uint32_t*)((nc < 4) ? g_k2 : g_v2);
#pragma unroll
          for (int i = 0; i < 2; ++i) {
            int row0 = pix0 + wm * 32 + i * 16 + (lane >> 2);
#pragma unroll
            for (int j = 0; j < 4; ++j) {
              int col = colb + j * 8 + 2 * (lane & 3);
              dst[((size_t)row0 * 256 + col) >> 1] = packh2(acc[i][j][0], acc[i][j][1]);
              dst[((size_t)(row0 + 8) * 256 + col) >> 1] = packh2(acc[i][j][2], acc[i][j][3]);
            }
          }
        }
      } else {
        const int t = pix0 >> 16, h = (pix0 >> 8) & 255, w0 = pix0 & 255;
        float* yb = y + (size_t)t * 16777216 + h * 256 + w0;
        for (int g = 0; g < 4; ++g) {
          if (wn == g) {
#pragma unroll
            for (int i = 0; i < 2; ++i) {
              int row0 = wm * 32 + i * 16 + (lane >> 2);
#pragma unroll
              for (int j = 0; j < 4; ++j) {
                int cl = j * 8 + 2 * (lane & 3);
                ys[cl * 68 + row0] = acc[i][j][0];
                ys[(cl + 1) * 68 + row0] = acc[i][j][1];
                ys[cl * 68 + row0 + 8] = acc[i][j][2];
                ys[(cl + 1) * 68 + row0 + 8] = acc[i][j][3];
              }
            }
          }
          __syncthreads();
          const int chb = nc * 128 + g * 32;
          for (int idx = tid; idx < 2048; idx += 256) {
            int cl = idx >> 6, p = idx & 63;
            yb[(size_t)(chb + cl) * 65536 + p] = ys[cl * 68 + p];
          }
          __syncthreads();
        }
      }
#pragma unroll
      for (int i = 0; i < 2; i++)
#pragma unroll
        for (int j = 0; j < 4; j++)
#pragma unroll
          for (int r = 0; r < 4; r++) acc[i][j][r] = 0.f;
    }
  }
}

// ---------------------------------------------------------------------------
// Tiled attention (R13): 8x4 px, 256 thr, fp16 halo 48KB, 3 blocks/SM.
// Epilogue stores plain fp16 o2 [pix][256].
// ---------------------------------------------------------------------------
__global__ void __launch_bounds__(256, 3) attn_kernel(const float* __restrict__ sims) {
  extern __shared__ char smc[];
  char* hsc = smc;                          // 49152 B: halo 96 cells x 256 ch fp16
  float* ls = (float*)(smc + 49152);        // 3328 fl
  float* sd = (float*)(smc + 62464);        // 832 fl
  float* ss = ls;                           // sims halo [9][96] overlay

  const int tid = threadIdx.x, lane = tid & 31, wid = tid >> 5;
  const int bw = blockIdx.x & 31;
  const int bh = (blockIdx.x >> 5) & 63;
  const int t = blockIdx.x >> 11;
  const int w0 = bw << 3, h0 = bh << 2;
  const uint32_t hs_a = smem_u32(hsc);

  const int r = wid & 3, seg = wid >> 2;
  const int hgrp = lane >> 3;
  const size_t pixg0 = (size_t)((t << 16) | ((h0 + r) << 8) | (w0 + (seg << 2)));

  const float4* qg = (const float4*)g_q;
  float4 qa[4], qb[4];
#pragma unroll
  for (int p = 0; p < 4; ++p) {
    qa[p] = qg[(pixg0 + p) * 64 + lane * 2];
    qb[p] = qg[(pixg0 + p) * 64 + lane * 2 + 1];
  }

  auto halo_async = [&](const __half* src) {
    const char* s = (const char*)src;
#pragma unroll 1
    for (int i = tid; i < 3072; i += 256) {
      int cell = i >> 5, c4 = i & 31;
      int rr = cell / 12, cc = cell - rr * 12;
      int gh = min(max(h0 - 2 + rr, 0), 255);
      int gw = min(max(w0 - 2 + cc, 0), 255);
      cp16(hs_a + (uint32_t)(cell * 512 + c4 * 16),
           s + (size_t)((t << 16) | (gh << 8) | gw) * 512 + c4 * 16);
    }
    CP_COMMIT();
  };

  // ---- P0: k halo async || sims halo + simdot ----
  halo_async(g_k2);
  for (int i = tid; i < 864; i += 256) {
    int s = i / 96, cell = i - s * 96;
    int rr = cell / 12, cc = cell - rr * 12;
    int gh = min(max(h0 - 2 + rr, 0), 255);
    int gw = min(max(w0 - 2 + cc, 0), 255);
    ss[i] = sims[(size_t)(((t * 9 + s) << 16) | (gh << 8) | gw)];
  }
  __syncthreads();
  for (int i = tid; i < 800; i += 256) {
    int px = i / 25, tap = i - px * 25;
    int rp = px >> 3, wp = px & 7;
    int di = tap / 5, dj = tap - di * 5;
    int ctr = (rp + 2) * 12 + wp + 2;
    int nbc = (rp + di) * 12 + wp + dj;
    float acc = 0.f;
#pragma unroll
    for (int s = 0; s < 9; ++s) acc += ss[s * 96 + ctr] * ss[s * 96 + nbc];
    sd[px * 26 + tap] = acc;
  }
  CP_WAIT0();
  __syncthreads();

  // ---- P1: logits ----
#pragma unroll 1
  for (int di = 0; di < 5; ++di) {
#pragma unroll
    for (int j = 0; j < 8; ++j) {
      const uint4 kv = *(const uint4*)(hsc + ((r + di) * 12 + (seg << 2) + j) * 512 +
                                       lane * 16);
      const __half2* kh = (const __half2*)&kv;
      float2 f0 = __half22float2(kh[0]), f1 = __half22float2(kh[1]);
      float2 f2 = __half22float2(kh[2]), f3 = __half22float2(kh[3]);
      const int plo = (j - 4 > 0) ? j - 4 : 0;
      const int phi = (j < 3) ? j : 3;
#pragma unroll
      for (int p = plo; p <= phi; ++p) {
        float d = qa[p].x * f0.x + qa[p].y * f0.y + qa[p].z * f1.x + qa[p].w * f1.y +
                  qb[p].x * f2.x + qb[p].y * f2.y + qb[p].z * f3.x + qb[p].w * f3.y;
        d += __shfl_xor_sync(0xffffffffu, d, 1);
        d += __shfl_xor_sync(0xffffffffu, d, 2);
        d += __shfl_xor_sync(0xffffffffu, d, 4);
        if ((lane & 7) == 0) {
          int px = (r << 3) + (seg << 2) + p;
          ls[(px * 4 + hgrp) * 26 + di * 5 + j - p] = d;
        }
      }
    }
  }
  __syncthreads();

  // ---- P2: v halo async || softmax + sim reweight ----
  halo_async(g_v2);
#pragma unroll 1
  for (int p = 0; p < 4; ++p) {
    const int px = (r << 3) + (seg << 2) + p;
#pragma unroll 1
    for (int h4 = 0; h4 < 4; ++h4) {
      float a = (lane < 25) ? ls[(px * 4 + h4) * 26 + lane] : -1e30f;
      float mx = a;
      mx = fmaxf(mx, __shfl_xor_sync(0xffffffffu, mx, 16));
      mx = fmaxf(mx, __shfl_xor_sync(0xffffffffu, mx, 8));
      mx = fmaxf(mx, __shfl_xor_sync(0xffffffffu, mx, 4));
      mx = fmaxf(mx, __shfl_xor_sync(0xffffffffu, mx, 2));
      mx = fmaxf(mx, __shfl_xor_sync(0xffffffffu, mx, 1));
      float e = (lane < 25) ? __expf(a - mx) * sd[px * 26 + lane] : 0.f;
      float s = e;
      s += __shfl_xor_sync(0xffffffffu, s, 16);
      s += __shfl_xor_sync(0xffffffffu, s, 8);
      s += __shfl_xor_sync(0xffffffffu, s, 4);
      s += __shfl_xor_sync(0xffffffffu, s, 2);
      s += __shfl_xor_sync(0xffffffffu, s, 1);
      if (lane < 25) ls[(px * 4 + h4) * 26 + lane] = e / (1e-10f + s);
    }
  }
  CP_WAIT0();
  __syncthreads();

  // ---- P3: weighted accumulate ----
  float acc[4][8];
#pragma unroll
  for (int p = 0; p < 4; ++p)
#pragma unroll
    for (int c = 0; c < 8; ++c) acc[p][c] = 0.f;

#pragma unroll 1
  for (int di = 0; di < 5; ++di) {
#pragma unroll
    for (int j = 0; j < 8; ++j) {
      const uint4 vv = *(const uint4*)(hsc + ((r + di) * 12 + (seg << 2) + j) * 512 +
                                       lane * 16);
      const __half2* vh = (const __half2*)&vv;
      float2 f0 = __half22float2(vh[0]), f1 = __half22float2(vh[1]);
      float2 f2 = __half22float2(vh[2]), f3 = __half22float2(vh[3]);
      const int plo = (j - 4 > 0) ? j - 4 : 0;
      const int phi = (j < 3) ? j : 3;
#pragma unroll
      for (int p = plo; p <= phi; ++p) {
        int px = (r << 3) + (seg << 2) + p;
        float wt = ls[(px * 4 + hgrp) * 26 + di * 5 + j - p];
        acc[p][0] += wt * f0.x; acc[p][1] += wt * f0.y;
        acc[p][2] += wt * f1.x; acc[p][3] += wt * f1.y;
        acc[p][4] += wt * f2.x; acc[p][5] += wt * f2.y;
        acc[p][6] += wt * f3.x; acc[p][7] += wt * f3.y;
      }
    }
  }

  // ---- store o2 plain fp16 [pix][256] ----
  uint4* oq = (uint4*)g_o2;
#pragma unroll
  for (int p = 0; p < 4; ++p) {
    uint4 hv;
    hv.x = packh2(acc[p][0], acc[p][1]);
    hv.y = packh2(acc[p][2], acc[p][3]);
    hv.z = packh2(acc[p][4], acc[p][5]);
    hv.w = packh2(acc[p][6], acc[p][7]);
    oq[(pixg0 + p) * 32 + lane] = hv;
  }
}

// ---------------------------------------------------------------------------
extern "C" void kernel_launch(void* const* d_in, const int* in_sizes, int n_in,
                              void* d_out, int out_size) {
  (void)in_sizes; (void)n_in; (void)out_size;
  const float* x = (const float*)d_in[0];
  const float* sims = (const float*)d_in[1];
  const float* Wq = (const float*)d_in[3];
  const float* Wk = (const float*)d_in[4];
  const float* Wv = (const float*)d_in[5];
  const float* Wp = (const float*)d_in[6];
  float* out = (float*)d_out;

  const int smem_gm = 1024 + 32768 + 32768 + 8704;  // 75264 -> 3 blocks/SM
  const int smem_at = 65792;                        // -> 3 blocks/SM
  cudaFuncSetAttribute(gemm_kernel, cudaFuncAttributeMaxDynamicSharedMemorySize, smem_gm);
  cudaFuncSetAttribute(attn_kernel, cudaFuncAttributeMaxDynamicSharedMemorySize, smem_at);

  __half *po2, *pw1, *pw2;
  cudaGetSymbolAddress((void**)&po2, g_o2);
  cudaGetSymbolAddress((void**)&pw1, g_w1);
  cudaGetSymbolAddress((void**)&pw2, g_w2);

  conv_w<<<1024, 256>>>(Wq, Wk, Wv, Wp);
  gemm_kernel<<<NPIX / 64, 256, smem_gm>>>(x, pw1, nullptr, 0);
  attn_kernel<<<8192, 256, smem_at>>>(sims);
  gemm_kernel<<<NPIX / 64, 256, smem_gm>>>(po2, pw2, out, 1);
}

// round 17
// speedup vs baseline: 2.7042x; 1.0414x over previous
#include <cuda_runtime.h>
#include <cuda_fp16.h>
#include <cstdint>

// ---------------------------------------------------------------------------
// SuperpixelAttention GB300 — Round 16: tensor-core attention.
//   gemm0: x fp32 -> q/k/v fp16 (single-term fp16 mma, fused conv)
//   attn : per 8x4 tile: S = Q.K^T via mma (per-head chunked SW128 halo),
//          in-register masked softmax (fp32) -> W fp16 smem,
//          O = W.V via mma (ldmatrix.trans B), store o fp16
//   gemm1: out = o @ Wp (single-term fp16 mma, transposed store)
// ---------------------------------------------------------------------------

#define NPIX 262144

__device__ __half g_q2[NPIX * 256];
__device__ __half g_k2[NPIX * 256];
__device__ __half g_v2[NPIX * 256];
__device__ __half g_o2[NPIX * 256];
__device__ __half g_w1[768 * 256];    // [n][k] fp16 (q scale folded)
__device__ __half g_w2[256 * 256];

__device__ __forceinline__ uint32_t smem_u32(const void* p) {
  uint32_t a;
  asm("{ .reg .u64 t; cvta.to.shared.u64 t, %1; cvt.u32.u64 %0, t; }"
      : "=r"(a) : "l"(p));
  return a;
}
#define SW128(o) ((o) ^ (((o) >> 3) & 0x70))

__device__ __forceinline__ void ldsm4(uint32_t& r0, uint32_t& r1, uint32_t& r2,
                                      uint32_t& r3, uint32_t a) {
  asm volatile("ldmatrix.sync.aligned.m8n8.x4.shared.b16 {%0,%1,%2,%3}, [%4];"
               : "=r"(r0), "=r"(r1), "=r"(r2), "=r"(r3) : "r"(a));
}
__device__ __forceinline__ void ldsm4t(uint32_t& r0, uint32_t& r1, uint32_t& r2,
                                       uint32_t& r3, uint32_t a) {
  asm volatile("ldmatrix.sync.aligned.m8n8.x4.trans.shared.b16 {%0,%1,%2,%3}, [%4];"
               : "=r"(r0), "=r"(r1), "=r"(r2), "=r"(r3) : "r"(a));
}
__device__ __forceinline__ void mma16816(float* c, const uint32_t* a,
                                         const uint32_t* b) {
  asm volatile(
      "mma.sync.aligned.m16n8k16.row.col.f32.f16.f16.f32 "
      "{%0,%1,%2,%3},{%4,%5,%6,%7},{%8,%9},{%0,%1,%2,%3};"
      : "+f"(c[0]), "+f"(c[1]), "+f"(c[2]), "+f"(c[3])
      : "r"(a[0]), "r"(a[1]), "r"(a[2]), "r"(a[3]), "r"(b[0]), "r"(b[1]));
}
__device__ __forceinline__ void cp16(uint32_t s, const void* g) {
  asm volatile("cp.async.cg.shared.global [%0], [%1], 16;" :: "r"(s), "l"(g));
}
#define CP_COMMIT() asm volatile("cp.async.commit_group;" ::: "memory")
#define CP_WAIT0()  asm volatile("cp.async.wait_group 0;" ::: "memory")

__device__ __forceinline__ uint32_t packh2(float a, float b) {
  __half2 h = __floats2half2_rn(a, b);
  return *reinterpret_cast<uint32_t*>(&h);
}

// ---------------------------------------------------------------------------
// conv_w: weights -> fp16 (q scale folded into Wq)
// ---------------------------------------------------------------------------
__global__ void __launch_bounds__(256) conv_w(const float* __restrict__ Wq,
                                              const float* __restrict__ Wk,
                                              const float* __restrict__ Wv,
                                              const float* __restrict__ Wp) {
  const int n = blockIdx.x;
  const int c = threadIdx.x;
  if (n < 768) {
    const float* Wm = (n < 256) ? Wq : ((n < 512) ? Wk : Wv);
    float v = Wm[c * 256 + (n & 255)];
    if (n < 256) v *= 0.125f;
    g_w1[(size_t)n * 256 + c] = __float2half_rn(v);
  } else {
    g_w2[(size_t)(n - 768) * 256 + c] = __float2half_rn(Wp[c * 256 + (n & 255)]);
  }
}

// ---------------------------------------------------------------------------
// fp16 single-term GEMM (R15 structure). mode 0: q/k/v all fp16 out.
// ---------------------------------------------------------------------------
__global__ void __launch_bounds__(256, 3) gemm_kernel(
    const void* __restrict__ Ain,
    const __half* __restrict__ B2,
    float* __restrict__ y, int mode) {
  extern __shared__ char dsm[];
  char* base = (char*)((((uintptr_t)dsm) + 1023) & ~(uintptr_t)1023);
  const uint32_t As_a = smem_u32(base);
  const uint32_t Bs_a0 = As_a + 32768u;
  float* ys = (float*)(base + 65536);

  const int tid = threadIdx.x, lane = tid & 31, wid = tid >> 5;
  const int wm = wid & 1, wn = wid >> 1;
  const int pix0 = blockIdx.x * 64;

  if (mode == 0) {
    const float* xf = (const float*)Ain;
    const int t = pix0 >> 16, h = (pix0 >> 8) & 255, w0 = pix0 & 255;
    const size_t gb = (size_t)t * 16777216 + h * 256 + w0;
#pragma unroll 4
    for (int idx = tid; idx < 8192; idx += 256) {
      int ce = (idx >> 6) << 1;
      int row = idx & 63;
      float f0 = xf[gb + (size_t)ce * 65536 + row];
      float f1 = xf[gb + (size_t)(ce + 1) * 65536 + row];
      int chunk = ce >> 6, cc = ce & 63;
      uint32_t addr = (uint32_t)(chunk * 8192) +
                      SW128((uint32_t)(row * 128 + (cc >> 3) * 16)) + (cc & 7) * 2;
      *(uint32_t*)(base + addr) = packh2(f0, f1);
    }
  } else {
    const uint4* Aq = (const uint4*)Ain;
    for (int idx = tid; idx < 2048; idx += 256) {
      int ch = idx >> 9, row = (idx >> 3) & 63, c = idx & 7;
      *(uint4*)(base + ch * 8192 + SW128((uint32_t)(row * 128 + c * 16))) =
          Aq[(size_t)(pix0 + row) * 32 + ch * 8 + c];
    }
  }

  const uint4* Bq = (const uint4*)B2;
  const int total = (mode ? 2 : 6) * 4;

  auto prefetchB = [&](int q) {
    int n0g = (q >> 2) << 7;
    int b8 = (q & 3) * 8;
    uint32_t buf = Bs_a0 + (uint32_t)((q & 1) << 14);
    for (int idx = tid; idx < 1024; idx += 256) {
      int row = idx >> 3, c = idx & 7;
      cp16(buf + SW128((uint32_t)(row * 128 + c * 16)),
           &Bq[(size_t)(n0g + row) * 32 + b8 + c]);
    }
    CP_COMMIT();
  };

  float acc[2][4][4];
#pragma unroll
  for (int i = 0; i < 2; i++)
#pragma unroll
    for (int j = 0; j < 4; j++)
#pragma unroll
      for (int r = 0; r < 4; r++) acc[i][j][r] = 0.f;

  prefetchB(0);

  const int arow_off = (lane & 7) + ((lane >> 3) & 1) * 8;
  const int ak_ex = ((lane >> 4) & 1) * 16;
  const int brow_off = (lane & 7) + ((lane >> 4) & 1) * 8;
  const int bk_ex = ((lane >> 3) & 1) * 16;

  for (int q = 0; q < total; ++q) {
    CP_WAIT0();
    __syncthreads();
    if (q + 1 < total) prefetchB(q + 1);

    const int ksub = q & 3;
    const uint32_t Ab = As_a + (uint32_t)(ksub * 8192);
    const uint32_t Bb = Bs_a0 + (uint32_t)((q & 1) << 14);

#pragma unroll
    for (int s = 0; s < 4; ++s) {
      uint32_t bf[4][2];
#pragma unroll
      for (int j2 = 0; j2 < 2; ++j2) {
        uint32_t off = (uint32_t)((wn * 32 + j2 * 16 + brow_off) * 128 + s * 32 + bk_ex);
        ldsm4(bf[2 * j2][0], bf[2 * j2][1], bf[2 * j2 + 1][0], bf[2 * j2 + 1][1],
              Bb + SW128(off));
      }
      uint32_t af[2][4];
#pragma unroll
      for (int i = 0; i < 2; ++i) {
        uint32_t off = (uint32_t)((wm * 32 + i * 16 + arow_off) * 128 + s * 32 + ak_ex);
        ldsm4(af[i][0], af[i][1], af[i][2], af[i][3], Ab + SW128(off));
      }
#pragma unroll
      for (int i = 0; i < 2; ++i)
#pragma unroll
        for (int j = 0; j < 4; ++j) mma16816(acc[i][j], af[i], bf[j]);
    }

    if (ksub == 3) {
      const int nc = q >> 2;
      if (mode == 0) {
        const int colb = (nc & 1) * 128 + wn * 32;
        uint32_t* dst = (uint32_t*)((nc < 2) ? g_q2 : (nc < 4) ? g_k2 : g_v2);
#pragma unroll
        for (int i = 0; i < 2; ++i) {
          int row0 = pix0 + wm * 32 + i * 16 + (lane >> 2);
#pragma unroll
          for (int j = 0; j < 4; ++j) {
            int col = colb + j * 8 + 2 * (lane & 3);
            dst[((size_t)row0 * 256 + col) >> 1] = packh2(acc[i][j][0], acc[i][j][1]);
            dst[((size_t)(row0 + 8) * 256 + col) >> 1] = packh2(acc[i][j][2], acc[i][j][3]);
          }
        }
      } else {
        const int t = pix0 >> 16, h = (pix0 >> 8) & 255, w0 = pix0 & 255;
        float* yb = y + (size_t)t * 16777216 + h * 256 + w0;
        for (int g = 0; g < 4; ++g) {
          if (wn == g) {
#pragma unroll
            for (int i = 0; i < 2; ++i) {
              int row0 = wm * 32 + i * 16 + (lane >> 2);
#pragma unroll
              for (int j = 0; j < 4; ++j) {
                int cl = j * 8 + 2 * (lane & 3);
                ys[cl * 68 + row0] = acc[i][j][0];
                ys[(cl + 1) * 68 + row0] = acc[i][j][1];
                ys[cl * 68 + row0 + 8] = acc[i][j][2];
                ys[(cl + 1) * 68 + row0 + 8] = acc[i][j][3];
              }
            }
          }
          __syncthreads();
          const int chb = nc * 128 + g * 32;
          for (int idx = tid; idx < 2048; idx += 256) {
            int cl = idx >> 6, p = idx & 63;
            yb[(size_t)(chb + cl) * 65536 + p] = ys[cl * 68 + p];
          }
          __syncthreads();
        }
      }
#pragma unroll
      for (int i = 0; i < 2; i++)
#pragma unroll
        for (int j = 0; j < 4; j++)
#pragma unroll
          for (int r = 0; r < 4; r++) acc[i][j][r] = 0.f;
    }
  }
}

// ---------------------------------------------------------------------------
// Tensor-core attention. Block = 8(w) x 4(h) px, 256 threads (8 warps).
// smem: halo 4x12288 (per-head SW128 chunks) | q 4x4096 | W 4x(32x208B) | sd
// Warp = (head = wid>>1, mh = wid&1). px row = rp*8+wp (rp = px>>3).
// ---------------------------------------------------------------------------
#define AT_HALO 0
#define AT_Q    49152
#define AT_W    65536
#define AT_SD   92160
#define AT_SMEM 95488

__global__ void __launch_bounds__(256, 2) attn_kernel(const float* __restrict__ sims) {
  extern __shared__ char smc[];
  const uint32_t sbase = smem_u32(smc);
  float* ss = (float*)(smc + AT_W);     // sims halo [9][96] (dead before W writes)
  float* sd = (float*)(smc + AT_SD);    // simdot [32][26]

  const int tid = threadIdx.x, lane = tid & 31, wid = tid >> 5;
  const int bw = blockIdx.x & 31;
  const int bh = (blockIdx.x >> 5) & 63;
  const int t = blockIdx.x >> 11;
  const int w0 = bw << 3, h0 = bh << 2;

  auto cellpix = [&](int cell) -> size_t {
    int rr = cell / 12, cc = cell - rr * 12;
    int gh = min(max(h0 - 2 + rr, 0), 255);
    int gw = min(max(w0 - 2 + cc, 0), 255);
    return (size_t)((t << 16) | (gh << 8) | gw);
  };

  auto halo_async = [&](const __half* src) {
    const char* s = (const char*)src;
#pragma unroll 1
    for (int i = tid; i < 3072; i += 256) {
      int cell = i >> 5, c4 = i & 31;
      cp16(sbase + (uint32_t)((c4 >> 3) * 12288 + SW128(cell * 128 + (c4 & 7) * 16)),
           s + cellpix(cell) * 512 + c4 * 16);
    }
    CP_COMMIT();
  };

  // ---- P0: k halo + q tile async || sims halo + simdot ----
  halo_async(g_k2);
  {
    const char* qs = (const char*)g_q2;
    for (int i = tid; i < 1024; i += 256) {
      int row = i >> 5, c4 = i & 31;
      int rp = row >> 3, wp = row & 7;
      size_t pix = (size_t)((t << 16) | ((h0 + rp) << 8) | (w0 + wp));
      cp16(sbase + AT_Q + (uint32_t)((c4 >> 3) * 4096 + SW128(row * 128 + (c4 & 7) * 16)),
           qs + pix * 512 + c4 * 16);
    }
    CP_COMMIT();
  }
  for (int i = tid; i < 864; i += 256) {
    int s = i / 96, cell = i - s * 96;
    ss[i] = sims[((size_t)(t * 9 + s) << 16) + (cellpix(cell) & 65535)];
  }
  __syncthreads();
  for (int i = tid; i < 800; i += 256) {
    int px = i / 25, tap = i - px * 25;
    int rp = px >> 3, wp = px & 7;
    int di = tap / 5, dj = tap - di * 5;
    int ctr = (rp + 2) * 12 + wp + 2;
    int nbc = (rp + di) * 12 + wp + dj;
    float a = 0.f;
#pragma unroll
    for (int s = 0; s < 9; ++s) a += ss[s * 96 + ctr] * ss[s * 96 + nbc];
    sd[px * 26 + tap] = a;
  }
  CP_WAIT0();
  __syncthreads();

  // ---- P1: logits mma  S[32,96] per head ----
  const int head = wid >> 1, mh = wid & 1;
  const int arow_off = (lane & 7) + ((lane >> 3) & 1) * 8;
  const int ak_ex = ((lane >> 4) & 1) * 16;
  const int brow_off = (lane & 7) + ((lane >> 4) & 1) * 8;
  const int bk_ex = ((lane >> 3) & 1) * 16;

  float acc[12][4];
#pragma unroll
  for (int j = 0; j < 12; ++j)
#pragma unroll
    for (int r = 0; r < 4; ++r) acc[j][r] = 0.f;

  {
    const uint32_t qb = sbase + AT_Q + (uint32_t)head * 4096u;
    const uint32_t kb = sbase + (uint32_t)head * 12288u;
#pragma unroll
    for (int s = 0; s < 4; ++s) {
      uint32_t af[4];
      ldsm4(af[0], af[1], af[2], af[3],
            qb + SW128((uint32_t)((mh * 16 + arow_off) * 128 + s * 32 + ak_ex)));
      uint32_t bf[12][2];
#pragma unroll
      for (int g = 0; g < 6; ++g)
        ldsm4(bf[2 * g][0], bf[2 * g][1], bf[2 * g + 1][0], bf[2 * g + 1][1],
              kb + SW128((uint32_t)((g * 16 + brow_off) * 128 + s * 32 + bk_ex)));
#pragma unroll
      for (int j = 0; j < 12; ++j) mma16816(acc[j], af, bf[j]);
    }
  }
  __syncthreads();  // all warps done reading k halo + q

  // ---- P2: v halo async || in-register masked softmax -> W fp16 ----
  halo_async(g_v2);
  {
    const int q4 = lane & 3;
    const int rowA = mh * 16 + (lane >> 2);
    const int rowB = rowA + 8;
    const int rpA = rowA >> 3, wpA = rowA & 7;
    const int rpB = rowB >> 3, wpB = rowB & 7;

    float mxA = -1e30f, mxB = -1e30f;
#pragma unroll
    for (int j = 0; j < 12; ++j)
#pragma unroll
      for (int i = 0; i < 2; ++i) {
        int cell = j * 8 + 2 * q4 + i;
        int rr = cell / 12, cc = cell - rr * 12;
        int diA = rr - rpA, djA = cc - wpA;
        if ((unsigned)diA < 5u && (unsigned)djA < 5u) mxA = fmaxf(mxA, acc[j][i]);
        int diB = rr - rpB, djB = cc - wpB;
        if ((unsigned)diB < 5u && (unsigned)djB < 5u) mxB = fmaxf(mxB, acc[j][2 + i]);
      }
    mxA = fmaxf(mxA, __shfl_xor_sync(0xffffffffu, mxA, 1));
    mxA = fmaxf(mxA, __shfl_xor_sync(0xffffffffu, mxA, 2));
    mxB = fmaxf(mxB, __shfl_xor_sync(0xffffffffu, mxB, 1));
    mxB = fmaxf(mxB, __shfl_xor_sync(0xffffffffu, mxB, 2));

    float sA = 0.f, sB = 0.f;
#pragma unroll
    for (int j = 0; j < 12; ++j)
#pragma unroll
      for (int i = 0; i < 2; ++i) {
        int cell = j * 8 + 2 * q4 + i;
        int rr = cell / 12, cc = cell - rr * 12;
        int diA = rr - rpA, djA = cc - wpA;
        float eA = 0.f;
        if ((unsigned)diA < 5u && (unsigned)djA < 5u)
          eA = __expf(acc[j][i] - mxA) * sd[rowA * 26 + diA * 5 + djA];
        acc[j][i] = eA; sA += eA;
        int diB = rr - rpB, djB = cc - wpB;
        float eB = 0.f;
        if ((unsigned)diB < 5u && (unsigned)djB < 5u)
          eB = __expf(acc[j][2 + i] - mxB) * sd[rowB * 26 + diB * 5 + djB];
        acc[j][2 + i] = eB; sB += eB;
      }
    sA += __shfl_xor_sync(0xffffffffu, sA, 1);
    sA += __shfl_xor_sync(0xffffffffu, sA, 2);
    sB += __shfl_xor_sync(0xffffffffu, sB, 1);
    sB += __shfl_xor_sync(0xffffffffu, sB, 2);
    const float invA = 1.f / (1e-10f + sA);
    const float invB = 1.f / (1e-10f + sB);

    char* Wb = smc + AT_W + head * 6656;
#pragma unroll
    for (int j = 0; j < 12; ++j) {
      int colb = (j * 8 + 2 * q4) * 2;  // byte offset (4-aligned)
      *(uint32_t*)(Wb + rowA * 208 + colb) = packh2(acc[j][0] * invA, acc[j][1] * invA);
      *(uint32_t*)(Wb + rowB * 208 + colb) = packh2(acc[j][2] * invB, acc[j][3] * invB);
    }
  }
  CP_WAIT0();
  __syncthreads();  // v halo + W visible

  // ---- P3: O = W x V per head ----
  {
    const int krow_off = (lane & 7) + ((lane >> 3) & 1) * 8;
    const int n_ex = ((lane >> 4) & 1) * 16;
    float oa[8][4];
#pragma unroll
    for (int j = 0; j < 8; ++j)
#pragma unroll
      for (int r = 0; r < 4; ++r) oa[j][r] = 0.f;

    const uint32_t Wb = sbase + AT_W + (uint32_t)head * 6656u;
    const uint32_t vb = sbase + (uint32_t)head * 12288u;
#pragma unroll
    for (int s = 0; s < 6; ++s) {
      uint32_t af[4];
      ldsm4(af[0], af[1], af[2], af[3],
            Wb + (uint32_t)((mh * 16 + arow_off) * 208 + s * 32 + ak_ex));
      uint32_t bv[8][2];
#pragma unroll
      for (int j2 = 0; j2 < 4; ++j2)
        ldsm4t(bv[2 * j2][0], bv[2 * j2][1], bv[2 * j2 + 1][0], bv[2 * j2 + 1][1],
               vb + SW128((uint32_t)((s * 16 + krow_off) * 128 + j2 * 32 + n_ex)));
#pragma unroll
      for (int j = 0; j < 8; ++j) mma16816(oa[j], af, bv[j]);
    }

    // store O -> g_o2 fp16 [pix][256]
    const int rowA = mh * 16 + (lane >> 2);
    const int rowB = rowA + 8;
    size_t pixA = (size_t)((t << 16) | ((h0 + (rowA >> 3)) << 8) | (w0 + (rowA & 7)));
    size_t pixB = (size_t)((t << 16) | ((h0 + (rowB >> 3)) << 8) | (w0 + (rowB & 7)));
    uint32_t* o32 = (uint32_t*)g_o2;
#pragma unroll
    for (int j = 0; j < 8; ++j) {
      int col = head * 64 + j * 8 + 2 * (lane & 3);
      o32[(pixA * 256 + col) >> 1] = packh2(oa[j][0], oa[j][1]);
      o32[(pixB * 256 + col) >> 1] = packh2(oa[j][2], oa[j][3]);
    }
  }
}

// ---------------------------------------------------------------------------
extern "C" void kernel_launch(void* const* d_in, const int* in_sizes, int n_in,
                              void* d_out, int out_size) {
  (void)in_sizes; (void)n_in; (void)out_size;
  const float* x = (const float*)d_in[0];
  const float* sims = (const float*)d_in[1];
  const float* Wq = (const float*)d_in[3];
  const float* Wk = (const float*)d_in[4];
  const float* Wv = (const float*)d_in[5];
  const float* Wp = (const float*)d_in[6];
  float* out = (float*)d_out;

  const int smem_gm = 1024 + 32768 + 32768 + 8704;  // 75264 -> 3 blocks/SM
  const int smem_at = AT_SMEM;                      // 95488 -> 2 blocks/SM
  cudaFuncSetAttribute(gemm_kernel, cudaFuncAttributeMaxDynamicSharedMemorySize, smem_gm);
  cudaFuncSetAttribute(attn_kernel, cudaFuncAttributeMaxDynamicSharedMemorySize, smem_at);

  __half *po2, *pw1, *pw2;
  cudaGetSymbolAddress((void**)&po2, g_o2);
  cudaGetSymbolAddress((void**)&pw1, g_w1);
  cudaGetSymbolAddress((void**)&pw2, g_w2);

  conv_w<<<1024, 256>>>(Wq, Wk, Wv, Wp);
  gemm_kernel<<<NPIX / 64, 256, smem_gm>>>(x, pw1, nullptr, 0);
  attn_kernel<<<8192, 256, smem_at>>>(sims);
  gemm_kernel<<<NPIX / 64, 256, smem_gm>>>(po2, pw2, out, 1);
}